// round 11
// baseline (speedup 1.0000x reference)
#include <cuda_runtime.h>
#include <cuda_fp16.h>
#include <math.h>
#include <stdint.h>

#define NHEADS 8
#define DMODEL 1024
#define DHEAD  128
#define KFDIM  3072
#define NSENT  2048
#define NKNOW  8192

// Scratch (no cudaMalloc allowed).
__device__ __half g_snth[NSENT * DMODEL];               // 4 MB  sentences fp16
__device__ __half g_wsh[NHEADS * DMODEL * DHEAD];       // 2 MB  w_s fp16
__device__ __half g_Sh[NHEADS * NSENT * DHEAD];         // 4 MB  S fp16
__device__ __half g_Kh[NHEADS * NKNOW * DHEAD];         // 16 MB K fp16
__device__ __half g_wkh[NHEADS * KFDIM * DHEAD];        // 6 MB  w_k fp16
__device__ float  g_colsum[NHEADS * NKNOW];             // 256 KB
__device__ __half g_invh[NHEADS * NKNOW];               // 128 KB 1/colsum fp16
__device__ __half g_Ah[(size_t)NHEADS * NSENT * NKNOW]; // 268 MB e fp16
__device__ __half g_Bh[(size_t)NKNOW * KFDIM];          // 50 MB knowledge fp16

// ===========================================================================
// helpers
// ===========================================================================
__device__ __forceinline__ void mma_f16(float* d, const uint32_t* a, const uint32_t* b) {
    asm volatile(
        "mma.sync.aligned.m16n8k16.row.col.f32.f16.f16.f32 "
        "{%0,%1,%2,%3}, {%4,%5,%6,%7}, {%8,%9}, {%0,%1,%2,%3};"
        : "+f"(d[0]), "+f"(d[1]), "+f"(d[2]), "+f"(d[3])
        : "r"(a[0]), "r"(a[1]), "r"(a[2]), "r"(a[3]), "r"(b[0]), "r"(b[1]));
}
__device__ __forceinline__ void cp_async16(uint32_t dst, const void* src) {
    asm volatile("cp.async.cg.shared.global [%0], [%1], 16;" :: "r"(dst), "l"(src));
}
__device__ __forceinline__ void ldsm_x4(uint32_t* r, uint32_t addr) {
    asm volatile("ldmatrix.sync.aligned.m8n8.x4.shared.b16 {%0,%1,%2,%3}, [%4];"
                 : "=r"(r[0]), "=r"(r[1]), "=r"(r[2]), "=r"(r[3]) : "r"(addr));
}
__device__ __forceinline__ void ldsm_x4_t(uint32_t* r, uint32_t addr) {
    asm volatile("ldmatrix.sync.aligned.m8n8.x4.trans.shared.b16 {%0,%1,%2,%3}, [%4];"
                 : "=r"(r[0]), "=r"(r[1]), "=r"(r[2]), "=r"(r[3]) : "r"(addr));
}
__device__ __forceinline__ uint32_t hmul2u(uint32_t a, uint32_t b) {
    uint32_t r;
    asm("mul.rn.f16x2 %0, %1, %2;" : "=r"(r) : "r"(a), "r"(b));
    return r;
}

// fp32 -> fp16 (rn)
__global__ __launch_bounds__(256)
void cvt_f16_kernel(const float* __restrict__ in, __half* __restrict__ out)
{
    size_t i = ((size_t)blockIdx.x * 256 + threadIdx.x) * 4;
    float4 v = *(const float4*)(in + i);
    *(__half2*)(out + i)     = __floats2half2_rn(v.x, v.y);
    *(__half2*)(out + i + 2) = __floats2half2_rn(v.z, v.w);
}

// ===========================================================================
// Merged S+K projection on fp16 tensor cores.
//   z in [0,8):  K proj head z;  z in [8,16): S proj head z-8
// ===========================================================================
#define KP_STG 4
#define KPA_STR 40
#define KPB_STR 136
#define KPA_H (128 * KPA_STR)
#define KPB_H (32 * KPB_STR)
#define KPSMEM (KP_STG * (KPA_H + KPB_H) * 2)   // 75776 B

__global__ void __launch_bounds__(256, 2)
proj_f16_merged(const __half* __restrict__ Ak, const __half* __restrict__ Wk,
                const float* __restrict__ bk, __half* __restrict__ Ok,
                const __half* __restrict__ As, const __half* __restrict__ Ws,
                const float* __restrict__ bs, __half* __restrict__ Os)
{
    const int zz = blockIdx.z;
    const bool isK = (zz < NHEADS);
    const int z = isK ? zz : zz - NHEADS;
    const int nyb = isK ? (NKNOW / 128) : (NSENT / 128);
    if (blockIdx.y >= nyb) return;

    const int Kdim = isK ? KFDIM : DMODEL;
    const int Mtot = isK ? NKNOW : NSENT;
    const __half* A = isK ? Ak : As;
    const __half* W = isK ? Wk : Ws;
    const float* bias = isK ? bk : bs;
    __half* out = isK ? Ok : Os;

    extern __shared__ __half kps[];
    const uint32_t sA = (uint32_t)__cvta_generic_to_shared(kps);
    const uint32_t sB = sA + KP_STG * KPA_H * 2;

    const int tid  = threadIdx.x;
    const int lane = tid & 31;
    const int wid  = tid >> 5;
    const int wm   = wid >> 2;
    const int wn   = wid & 3;
    const int m0   = blockIdx.y * 128;

    const __half* Ap = A + (size_t)m0 * Kdim;
    const __half* Bp = W + (size_t)z * Kdim * DHEAD;

    const int a_r = tid >> 1;
    const int a_c = (tid & 1) << 4;
    const int b_r = tid >> 3;
    const int b_c = (tid & 7) << 4;

    float acc[4][4][4];
#pragma unroll
    for (int mt = 0; mt < 4; mt++)
#pragma unroll
        for (int nt = 0; nt < 4; nt++)
#pragma unroll
            for (int r = 0; r < 4; r++) acc[mt][nt][r] = 0.f;

    const int NT = Kdim / 32;

    auto issue = [&](int kt, int s) {
#pragma unroll
        for (int i = 0; i < 2; i++)
            cp_async16(sA + (uint32_t)(s * KPA_H + a_r * KPA_STR + a_c + 8 * i) * 2,
                       Ap + (size_t)a_r * Kdim + kt * 32 + a_c + 8 * i);
#pragma unroll
        for (int i = 0; i < 2; i++)
            cp_async16(sB + (uint32_t)(s * KPB_H + b_r * KPB_STR + b_c + 8 * i) * 2,
                       Bp + (size_t)(kt * 32 + b_r) * DHEAD + b_c + 8 * i);
        asm volatile("cp.async.commit_group;" ::: "memory");
    };

    issue(0, 0); issue(1, 1); issue(2, 2);

    int scur = 0;
    for (int kt = 0; kt < NT; kt++) {
        if (kt < NT - 2)       asm volatile("cp.async.wait_group 2;" ::: "memory");
        else if (kt == NT - 2) asm volatile("cp.async.wait_group 1;" ::: "memory");
        else                   asm volatile("cp.async.wait_group 0;" ::: "memory");
        __syncthreads();

        if (kt + 3 < NT) {
            int snx = scur + 3; if (snx >= KP_STG) snx -= KP_STG;
            issue(kt + 3, snx);
        }

        const uint32_t aB = sA + (uint32_t)(scur * KPA_H) * 2;
        const uint32_t bB = sB + (uint32_t)(scur * KPB_H) * 2;

#pragma unroll
        for (int ks = 0; ks < 2; ks++) {
            uint32_t bf[4][2];
#pragma unroll
            for (int ntp = 0; ntp < 2; ntp++) {
                uint32_t r[4];
                uint32_t addr = bB + (uint32_t)(((ks * 16 + (lane & 15)) * KPB_STR
                               + wn * 32 + ntp * 16 + ((lane >> 4) << 3)) * 2);
                ldsm_x4_t(r, addr);
                bf[2 * ntp][0]     = r[0];
                bf[2 * ntp][1]     = r[1];
                bf[2 * ntp + 1][0] = r[2];
                bf[2 * ntp + 1][1] = r[3];
            }
#pragma unroll
            for (int mt = 0; mt < 4; mt++) {
                uint32_t af[4];
                uint32_t addr = aB + (uint32_t)(((wm * 64 + mt * 16 + (lane & 15)) * KPA_STR
                               + ks * 16 + ((lane >> 4) << 3)) * 2);
                ldsm_x4(af, addr);
#pragma unroll
                for (int nt = 0; nt < 4; nt++)
                    mma_f16(acc[mt][nt], af, bf[nt]);
            }
        }
        scur++; if (scur >= KP_STG) scur -= KP_STG;
        __syncthreads();
    }

    __half* Op = out + (size_t)z * Mtot * DHEAD;
#pragma unroll
    for (int mt = 0; mt < 4; mt++) {
        const int r = m0 + wm * 64 + mt * 16 + (lane >> 2);
#pragma unroll
        for (int nt = 0; nt < 4; nt++) {
            const int c = wn * 32 + nt * 8 + ((lane & 3) << 1);
            float b0 = bias[z * DHEAD + c], b1 = bias[z * DHEAD + c + 1];
            *(__half2*)(Op + (size_t)r * DHEAD + c) =
                __floats2half2_rn(acc[mt][nt][0] + b0, acc[mt][nt][1] + b1);
            *(__half2*)(Op + (size_t)(r + 8) * DHEAD + c) =
                __floats2half2_rn(acc[mt][nt][2] + b0, acc[mt][nt][3] + b1);
        }
    }
}

// ===========================================================================
// Scores on fp16 tensor cores (NT) + fp32 exp; writes fp16 e + colsum.
// ===========================================================================
#define SC_STR 136
#define SC_SMEM (2 * 128 * SC_STR * 2)

__global__ void __launch_bounds__(256, 2)
scores_f16_kernel(float scale)
{
    extern __shared__ __half scs[];
    const uint32_t sA = (uint32_t)__cvta_generic_to_shared(scs);
    const uint32_t sB = sA + 128 * SC_STR * 2;
    __shared__ float red[16][128];

    const int tid  = threadIdx.x;
    const int lane = tid & 31;
    const int wid  = tid >> 5;
    const int wm   = wid >> 2;
    const int wn   = wid & 3;
    const int z    = blockIdx.z;
    const int m0   = blockIdx.y * 128;
    const int n0   = blockIdx.x * 128;

    const __half* Ap = g_Sh + (size_t)z * NSENT * DHEAD + (size_t)m0 * DHEAD;
    const __half* Bp = g_Kh + (size_t)z * NKNOW * DHEAD + (size_t)n0 * DHEAD;

    {
        const int r  = tid >> 1;
        const int c0 = (tid & 1) << 6;
#pragma unroll
        for (int i = 0; i < 8; i++) {
            cp_async16(sA + (uint32_t)(r * SC_STR + c0 + 8 * i) * 2,
                       Ap + (size_t)r * DHEAD + c0 + 8 * i);
            cp_async16(sB + (uint32_t)(r * SC_STR + c0 + 8 * i) * 2,
                       Bp + (size_t)r * DHEAD + c0 + 8 * i);
        }
        asm volatile("cp.async.commit_group;" ::: "memory");
        asm volatile("cp.async.wait_group 0;" ::: "memory");
        __syncthreads();
    }

    float acc[4][4][4];
#pragma unroll
    for (int mt = 0; mt < 4; mt++)
#pragma unroll
        for (int nt = 0; nt < 4; nt++)
#pragma unroll
            for (int r = 0; r < 4; r++) acc[mt][nt][r] = 0.f;

#pragma unroll
    for (int ks = 0; ks < 8; ks++) {
        uint32_t bf[4][2];
#pragma unroll
        for (int ntp = 0; ntp < 2; ntp++) {
            uint32_t r[4];
            uint32_t addr = sB + (uint32_t)(((wn * 32 + ntp * 16 + (lane & 15)) * SC_STR
                           + ks * 16 + ((lane >> 4) << 3)) * 2);
            ldsm_x4(r, addr);
            bf[2 * ntp][0]     = r[0];
            bf[2 * ntp][1]     = r[2];
            bf[2 * ntp + 1][0] = r[1];
            bf[2 * ntp + 1][1] = r[3];
        }
#pragma unroll
        for (int mt = 0; mt < 4; mt++) {
            uint32_t af[4];
            uint32_t addr = sA + (uint32_t)(((wm * 64 + mt * 16 + (lane & 15)) * SC_STR
                           + ks * 16 + ((lane >> 4) << 3)) * 2);
            ldsm_x4(af, addr);
#pragma unroll
            for (int nt = 0; nt < 4; nt++)
                mma_f16(acc[mt][nt], af, bf[nt]);
        }
    }

    float cp[8];
#pragma unroll
    for (int j = 0; j < 8; j++) cp[j] = 0.f;
    __half* Ep = g_Ah + (size_t)z * NSENT * NKNOW;
#pragma unroll
    for (int mt = 0; mt < 4; mt++) {
        const int r = m0 + wm * 64 + mt * 16 + (lane >> 2);
#pragma unroll
        for (int nt = 0; nt < 4; nt++) {
            const int c = n0 + wn * 32 + nt * 8 + ((lane & 3) << 1);
            float e0 = __expf(acc[mt][nt][0] * scale);
            float e1 = __expf(acc[mt][nt][1] * scale);
            float e2 = __expf(acc[mt][nt][2] * scale);
            float e3 = __expf(acc[mt][nt][3] * scale);
            *(__half2*)(Ep + (size_t)r * NKNOW + c)       = __floats2half2_rn(e0, e1);
            *(__half2*)(Ep + (size_t)(r + 8) * NKNOW + c) = __floats2half2_rn(e2, e3);
            cp[nt * 2]     += e0 + e2;
            cp[nt * 2 + 1] += e1 + e3;
        }
    }
    const int rr = wm * 8 + (lane >> 2);
#pragma unroll
    for (int nt = 0; nt < 4; nt++) {
        red[rr][wn * 32 + nt * 8 + ((lane & 3) << 1)]     = cp[nt * 2];
        red[rr][wn * 32 + nt * 8 + ((lane & 3) << 1) + 1] = cp[nt * 2 + 1];
    }
    __syncthreads();
    if (tid < 128) {
        float s = 0.f;
#pragma unroll
        for (int r = 0; r < 16; r++) s += red[r][tid];
        atomicAdd(&g_colsum[(size_t)z * NKNOW + n0 + tid], s);
    }
}

// ===========================================================================
// inv kernel: g_invh = fp16(1/colsum)
// ===========================================================================
__global__ __launch_bounds__(256)
void inv_kernel()
{
    int i = blockIdx.x * 256 + threadIdx.x;
    g_invh[i] = __float2half_rn(1.f / g_colsum[i]);
}

// ===========================================================================
// Normalize: attn fp32 = e * (1/colsum).  (fp16 normalized copy eliminated —
// fused kernel scales fragments by g_invh in-register.)
// ===========================================================================
__global__ __launch_bounds__(256)
void normalize_kernel(float* __restrict__ attn)
{
    const int h = blockIdx.z;
    const int m = (blockIdx.x * 256 + threadIdx.x) * 2;
    const int n0 = blockIdx.y * 64;
    float2 cs = *(const float2*)&g_colsum[(size_t)h * NKNOW + m];
    const float iv0 = 1.f / cs.x, iv1 = 1.f / cs.y;
    const size_t base = (size_t)h * NSENT * NKNOW + (size_t)n0 * NKNOW + m;
    float*  p   = attn + base;
    const __half* p16 = g_Ah + base;
#pragma unroll 4
    for (int nn = 0; nn < 64; nn++) {
        size_t idx = (size_t)nn * NKNOW;
        __half2 e = *(const __half2*)(p16 + idx);
        *(float2*)(p + idx) = make_float2(__half2float(__low2half(e))  * iv0,
                                          __half2float(__high2half(e)) * iv1);
    }
}

// ===========================================================================
// fused = (e .* inv) @ knowledge  (fp16 mma, fp32 accum, in-register scaling)
//   CTA 128x256xK64, 256 thr (8 warps 2x4, warp tile 64x64), 4-stage cp.async
//   smem reads/chunk: 4x16KB (A) + 2x32KB (B) = 128 KB (was 192 with 16 warps)
// ===========================================================================
#define FBM 128
#define FBN 256
#define FBK 64
#define FSTG 4
#define SA_STR 72
#define SB_STR 264
#define SA_H (FBM * SA_STR)
#define SB_H (FBK * SB_STR)
#define FSMEM (FSTG * (SA_H + SB_H) * 2)    // 208896 B

__global__ void __launch_bounds__(256, 1)
fused_mma_f16(float* __restrict__ C)
{
    extern __shared__ __half smh[];
    const uint32_t sA_u32 = (uint32_t)__cvta_generic_to_shared(smh);
    const uint32_t sB_u32 = sA_u32 + FSTG * SA_H * 2;

    const int tid  = threadIdx.x;
    const int lane = tid & 31;
    const int wid  = tid >> 5;
    const int wm   = wid & 1;        // 2 m-groups (64 rows)
    const int wn   = wid >> 1;       // 4 n-groups (64 cols)
    const int z    = blockIdx.z;
    const int m0   = blockIdx.y * FBM;
    const int n0   = blockIdx.x * FBN;

    const __half* Ap = g_Ah + (size_t)z * NSENT * NKNOW + (size_t)m0 * NKNOW;
    const __half* Bp = g_Bh + n0;
    const __half* invp = g_invh + (size_t)z * NKNOW;

    // loaders (256 threads)
    const int a_row = tid >> 1;              // 0..127
    const int a_ch  = (tid & 1) << 5;        // 0 or 32 halves, 4 cp16 each
    const int b_row = tid >> 3;              // 0..31 (+32)
    const int b_ch  = (tid & 7) << 5;        // 0..224, 4 cp16 each

    float acc[4][8][4];
#pragma unroll
    for (int mt = 0; mt < 4; mt++)
#pragma unroll
        for (int nt = 0; nt < 8; nt++)
#pragma unroll
            for (int r = 0; r < 4; r++) acc[mt][nt][r] = 0.f;

    const int NT = NKNOW / FBK;              // 128

    auto issue = [&](int kt, int s) {
        const __half* abase = Ap + (size_t)kt * FBK;
#pragma unroll
        for (int i = 0; i < 4; i++)
            cp_async16(sA_u32 + (uint32_t)(s * SA_H + a_row * SA_STR + a_ch + 8 * i) * 2,
                       abase + (size_t)a_row * NKNOW + a_ch + 8 * i);
        const __half* bbase = Bp + (size_t)(kt * FBK) * KFDIM;
#pragma unroll
        for (int p = 0; p < 2; p++) {
            int row = b_row + p * 32;
#pragma unroll
            for (int i = 0; i < 4; i++)
                cp_async16(sB_u32 + (uint32_t)(s * SB_H + row * SB_STR + b_ch + 8 * i) * 2,
                           bbase + (size_t)row * KFDIM + b_ch + 8 * i);
        }
        asm volatile("cp.async.commit_group;" ::: "memory");
    };

    issue(0, 0); issue(1, 1); issue(2, 2);

    int scur = 0;
    for (int kt = 0; kt < NT; kt++) {
        if (kt < NT - 2)       asm volatile("cp.async.wait_group 2;" ::: "memory");
        else if (kt == NT - 2) asm volatile("cp.async.wait_group 1;" ::: "memory");
        else                   asm volatile("cp.async.wait_group 0;" ::: "memory");
        __syncthreads();

        if (kt + 3 < NT) {
            int snx = scur + 3; if (snx >= FSTG) snx -= FSTG;
            issue(kt + 3, snx);
        }

        const uint32_t aBase = sA_u32 + (uint32_t)(scur * SA_H) * 2;
        const uint32_t bBase = sB_u32 + (uint32_t)(scur * SB_H) * 2;
        const __half2* ivb = (const __half2*)(invp + (size_t)kt * FBK);

#pragma unroll
        for (int ks = 0; ks < 4; ks++) {
            // inv pairs for this k-slice: regs a0/a1 use k=2c,2c+1; a2/a3 k+8
            uint32_t iv0 = *(const uint32_t*)(ivb + ks * 8 + (lane & 3));
            uint32_t iv1 = *(const uint32_t*)(ivb + ks * 8 + 4 + (lane & 3));

            uint32_t bf[8][2];
#pragma unroll
            for (int ntp = 0; ntp < 4; ntp++) {
                uint32_t r[4];
                uint32_t addr = bBase + (uint32_t)(((ks * 16 + (lane & 15)) * SB_STR
                               + wn * 64 + ntp * 16 + ((lane >> 4) << 3)) * 2);
                ldsm_x4_t(r, addr);
                bf[2 * ntp][0]     = r[0];
                bf[2 * ntp][1]     = r[1];
                bf[2 * ntp + 1][0] = r[2];
                bf[2 * ntp + 1][1] = r[3];
            }
#pragma unroll
            for (int mt = 0; mt < 4; mt++) {
                uint32_t af[4];
                uint32_t addr = aBase + (uint32_t)(((wm * 64 + mt * 16 + (lane & 15)) * SA_STR
                               + ks * 16 + ((lane >> 4) << 3)) * 2);
                ldsm_x4(af, addr);
                af[0] = hmul2u(af[0], iv0);
                af[1] = hmul2u(af[1], iv0);
                af[2] = hmul2u(af[2], iv1);
                af[3] = hmul2u(af[3], iv1);
#pragma unroll
                for (int nt = 0; nt < 8; nt++)
                    mma_f16(acc[mt][nt], af, bf[nt]);
            }
        }
        scur++; if (scur >= FSTG) scur -= FSTG;
    }

    const int ldc = NHEADS * KFDIM;
#pragma unroll
    for (int mt = 0; mt < 4; mt++) {
        const int r = m0 + wm * 64 + mt * 16 + (lane >> 2);
#pragma unroll
        for (int nt = 0; nt < 8; nt++) {
            const int c = z * KFDIM + n0 + wn * 64 + nt * 8 + ((lane & 3) << 1);
            *(float2*)(C + (size_t)r * ldc + c)       = make_float2(acc[mt][nt][0], acc[mt][nt][1]);
            *(float2*)(C + (size_t)(r + 8) * ldc + c) = make_float2(acc[mt][nt][2], acc[mt][nt][3]);
        }
    }
}

// ===========================================================================
// Host side
// ===========================================================================
extern "C" void kernel_launch(void* const* d_in, const int* in_sizes, int n_in,
                              void* d_out, int out_size)
{
    const float* sentences = (const float*)d_in[0];
    const float* knowledge = (const float*)d_in[1];
    const float* w_s       = (const float*)d_in[2];
    const float* b_s       = (const float*)d_in[3];
    const float* w_k       = (const float*)d_in[4];
    const float* b_k       = (const float*)d_in[5];

    float* attn  = (float*)d_out;
    float* fused = (float*)d_out + (size_t)NHEADS * NSENT * NKNOW;

    float* csum = nullptr;
    __half *snth = nullptr, *wsh = nullptr, *Sh = nullptr, *Kh = nullptr,
           *wkh = nullptr, *Bh = nullptr;
    cudaGetSymbolAddress((void**)&csum, g_colsum);
    cudaGetSymbolAddress((void**)&snth, g_snth);
    cudaGetSymbolAddress((void**)&wsh,  g_wsh);
    cudaGetSymbolAddress((void**)&Sh,   g_Sh);
    cudaGetSymbolAddress((void**)&Kh,   g_Kh);
    cudaGetSymbolAddress((void**)&wkh,  g_wkh);
    cudaGetSymbolAddress((void**)&Bh,   g_Bh);

    static bool attrs_set = false;
    if (!attrs_set) {
        cudaFuncSetAttribute(proj_f16_merged,
                             cudaFuncAttributeMaxDynamicSharedMemorySize, KPSMEM);
        cudaFuncSetAttribute(scores_f16_kernel,
                             cudaFuncAttributeMaxDynamicSharedMemorySize, SC_SMEM);
        cudaFuncSetAttribute(fused_mma_f16,
                             cudaFuncAttributeMaxDynamicSharedMemorySize, FSMEM);
        attrs_set = true;
    }

    // 0) zero colsums; fp16 conversions
    cudaMemsetAsync(csum, 0, (size_t)NHEADS * NKNOW * sizeof(float));
    cvt_f16_kernel<<<((size_t)NKNOW * KFDIM) / 1024, 256>>>(knowledge, Bh);
    cvt_f16_kernel<<<((size_t)NHEADS * KFDIM * DHEAD) / 1024, 256>>>(w_k, wkh);
    cvt_f16_kernel<<<((size_t)NSENT * DMODEL) / 1024, 256>>>(sentences, snth);
    cvt_f16_kernel<<<((size_t)NHEADS * DMODEL * DHEAD) / 1024, 256>>>(w_s, wsh);

    // 1+2) merged S & K projections (fp16 mma)
    {
        dim3 grid(1, NKNOW / 128, 2 * NHEADS);
        proj_f16_merged<<<grid, 256, KPSMEM>>>(Bh, wkh, b_k, Kh,
                                               snth, wsh, b_s, Sh);
    }
    // 3) scores + exp -> fp16 e + colsum
    {
        dim3 grid(NKNOW / 128, NSENT / 128, NHEADS);
        scores_f16_kernel<<<grid, 256, SC_SMEM>>>(0.08838834764831845f);
    }
    // 4) inv + normalize (fp32 attn output only)
    inv_kernel<<<(NHEADS * NKNOW) / 256, 256>>>();
    {
        dim3 grid(NKNOW / 512, NSENT / 64, NHEADS);
        normalize_kernel<<<grid, 256>>>(attn);
    }
    // 5) fused GEMM (fp16 mma, warp tile 64x64, in-register inv scaling)
    {
        dim3 grid(KFDIM / FBN, NSENT / FBM, NHEADS);
        fused_mma_f16<<<grid, 256, FSMEM>>>(fused);
    }
}

// round 12
// speedup vs baseline: 1.1776x; 1.1776x over previous
#include <cuda_runtime.h>
#include <cuda_fp16.h>
#include <math.h>
#include <stdint.h>

#define NHEADS 8
#define DMODEL 1024
#define DHEAD  128
#define KFDIM  3072
#define NSENT  2048
#define NKNOW  8192

// Scratch (no cudaMalloc allowed).
__device__ __half g_snth[NSENT * DMODEL];               // 4 MB  sentences fp16
__device__ __half g_wsh[NHEADS * DMODEL * DHEAD];       // 2 MB  w_s fp16
__device__ __half g_Sh[NHEADS * NSENT * DHEAD];         // 4 MB  S fp16
__device__ __half g_Kh[NHEADS * NKNOW * DHEAD];         // 16 MB K fp16
__device__ __half g_wkh[NHEADS * KFDIM * DHEAD];        // 6 MB  w_k fp16
__device__ float  g_colsum[NHEADS * NKNOW];             // 256 KB
__device__ __half g_invh[NHEADS * NKNOW];               // 128 KB 1/colsum fp16
__device__ __half g_Ah[(size_t)NHEADS * NSENT * NKNOW]; // 268 MB e fp16
__device__ __half g_Bh[(size_t)NKNOW * KFDIM];          // 50 MB knowledge fp16

// ===========================================================================
// helpers
// ===========================================================================
__device__ __forceinline__ void mma_f16(float* d, const uint32_t* a, const uint32_t* b) {
    asm volatile(
        "mma.sync.aligned.m16n8k16.row.col.f32.f16.f16.f32 "
        "{%0,%1,%2,%3}, {%4,%5,%6,%7}, {%8,%9}, {%0,%1,%2,%3};"
        : "+f"(d[0]), "+f"(d[1]), "+f"(d[2]), "+f"(d[3])
        : "r"(a[0]), "r"(a[1]), "r"(a[2]), "r"(a[3]), "r"(b[0]), "r"(b[1]));
}
__device__ __forceinline__ void cp_async16(uint32_t dst, const void* src) {
    asm volatile("cp.async.cg.shared.global [%0], [%1], 16;" :: "r"(dst), "l"(src));
}
__device__ __forceinline__ void ldsm_x4(uint32_t* r, uint32_t addr) {
    asm volatile("ldmatrix.sync.aligned.m8n8.x4.shared.b16 {%0,%1,%2,%3}, [%4];"
                 : "=r"(r[0]), "=r"(r[1]), "=r"(r[2]), "=r"(r[3]) : "r"(addr));
}
__device__ __forceinline__ void ldsm_x4_t(uint32_t* r, uint32_t addr) {
    asm volatile("ldmatrix.sync.aligned.m8n8.x4.trans.shared.b16 {%0,%1,%2,%3}, [%4];"
                 : "=r"(r[0]), "=r"(r[1]), "=r"(r[2]), "=r"(r[3]) : "r"(addr));
}
__device__ __forceinline__ uint32_t hmul2u(uint32_t a, uint32_t b) {
    uint32_t r;
    asm("mul.rn.f16x2 %0, %1, %2;" : "=r"(r) : "r"(a), "r"(b));
    return r;
}

// fp32 -> fp16 (rn)
__global__ __launch_bounds__(256)
void cvt_f16_kernel(const float* __restrict__ in, __half* __restrict__ out)
{
    size_t i = ((size_t)blockIdx.x * 256 + threadIdx.x) * 4;
    float4 v = *(const float4*)(in + i);
    *(__half2*)(out + i)     = __floats2half2_rn(v.x, v.y);
    *(__half2*)(out + i + 2) = __floats2half2_rn(v.z, v.w);
}

// ===========================================================================
// Merged S+K projection on fp16 tensor cores.
//   z in [0,8):  K proj head z;  z in [8,16): S proj head z-8
// ===========================================================================
#define KP_STG 4
#define KPA_STR 40
#define KPB_STR 136
#define KPA_H (128 * KPA_STR)
#define KPB_H (32 * KPB_STR)
#define KPSMEM (KP_STG * (KPA_H + KPB_H) * 2)   // 75776 B

__global__ void __launch_bounds__(256, 2)
proj_f16_merged(const __half* __restrict__ Ak, const __half* __restrict__ Wk,
                const float* __restrict__ bk, __half* __restrict__ Ok,
                const __half* __restrict__ As, const __half* __restrict__ Ws,
                const float* __restrict__ bs, __half* __restrict__ Os)
{
    const int zz = blockIdx.z;
    const bool isK = (zz < NHEADS);
    const int z = isK ? zz : zz - NHEADS;
    const int nyb = isK ? (NKNOW / 128) : (NSENT / 128);
    if (blockIdx.y >= nyb) return;

    const int Kdim = isK ? KFDIM : DMODEL;
    const int Mtot = isK ? NKNOW : NSENT;
    const __half* A = isK ? Ak : As;
    const __half* W = isK ? Wk : Ws;
    const float* bias = isK ? bk : bs;
    __half* out = isK ? Ok : Os;

    extern __shared__ __half kps[];
    const uint32_t sA = (uint32_t)__cvta_generic_to_shared(kps);
    const uint32_t sB = sA + KP_STG * KPA_H * 2;

    const int tid  = threadIdx.x;
    const int lane = tid & 31;
    const int wid  = tid >> 5;
    const int wm   = wid >> 2;
    const int wn   = wid & 3;
    const int m0   = blockIdx.y * 128;

    const __half* Ap = A + (size_t)m0 * Kdim;
    const __half* Bp = W + (size_t)z * Kdim * DHEAD;

    const int a_r = tid >> 1;
    const int a_c = (tid & 1) << 4;
    const int b_r = tid >> 3;
    const int b_c = (tid & 7) << 4;

    float acc[4][4][4];
#pragma unroll
    for (int mt = 0; mt < 4; mt++)
#pragma unroll
        for (int nt = 0; nt < 4; nt++)
#pragma unroll
            for (int r = 0; r < 4; r++) acc[mt][nt][r] = 0.f;

    const int NT = Kdim / 32;

    auto issue = [&](int kt, int s) {
#pragma unroll
        for (int i = 0; i < 2; i++)
            cp_async16(sA + (uint32_t)(s * KPA_H + a_r * KPA_STR + a_c + 8 * i) * 2,
                       Ap + (size_t)a_r * Kdim + kt * 32 + a_c + 8 * i);
#pragma unroll
        for (int i = 0; i < 2; i++)
            cp_async16(sB + (uint32_t)(s * KPB_H + b_r * KPB_STR + b_c + 8 * i) * 2,
                       Bp + (size_t)(kt * 32 + b_r) * DHEAD + b_c + 8 * i);
        asm volatile("cp.async.commit_group;" ::: "memory");
    };

    issue(0, 0); issue(1, 1); issue(2, 2);

    int scur = 0;
    for (int kt = 0; kt < NT; kt++) {
        if (kt < NT - 2)       asm volatile("cp.async.wait_group 2;" ::: "memory");
        else if (kt == NT - 2) asm volatile("cp.async.wait_group 1;" ::: "memory");
        else                   asm volatile("cp.async.wait_group 0;" ::: "memory");
        __syncthreads();

        if (kt + 3 < NT) {
            int snx = scur + 3; if (snx >= KP_STG) snx -= KP_STG;
            issue(kt + 3, snx);
        }

        const uint32_t aB = sA + (uint32_t)(scur * KPA_H) * 2;
        const uint32_t bB = sB + (uint32_t)(scur * KPB_H) * 2;

#pragma unroll
        for (int ks = 0; ks < 2; ks++) {
            uint32_t bf[4][2];
#pragma unroll
            for (int ntp = 0; ntp < 2; ntp++) {
                uint32_t r[4];
                uint32_t addr = bB + (uint32_t)(((ks * 16 + (lane & 15)) * KPB_STR
                               + wn * 32 + ntp * 16 + ((lane >> 4) << 3)) * 2);
                ldsm_x4_t(r, addr);
                bf[2 * ntp][0]     = r[0];
                bf[2 * ntp][1]     = r[1];
                bf[2 * ntp + 1][0] = r[2];
                bf[2 * ntp + 1][1] = r[3];
            }
#pragma unroll
            for (int mt = 0; mt < 4; mt++) {
                uint32_t af[4];
                uint32_t addr = aB + (uint32_t)(((wm * 64 + mt * 16 + (lane & 15)) * KPA_STR
                               + ks * 16 + ((lane >> 4) << 3)) * 2);
                ldsm_x4(af, addr);
#pragma unroll
                for (int nt = 0; nt < 4; nt++)
                    mma_f16(acc[mt][nt], af, bf[nt]);
            }
        }
        scur++; if (scur >= KP_STG) scur -= KP_STG;
        __syncthreads();
    }

    __half* Op = out + (size_t)z * Mtot * DHEAD;
#pragma unroll
    for (int mt = 0; mt < 4; mt++) {
        const int r = m0 + wm * 64 + mt * 16 + (lane >> 2);
#pragma unroll
        for (int nt = 0; nt < 4; nt++) {
            const int c = wn * 32 + nt * 8 + ((lane & 3) << 1);
            float b0 = bias[z * DHEAD + c], b1 = bias[z * DHEAD + c + 1];
            *(__half2*)(Op + (size_t)r * DHEAD + c) =
                __floats2half2_rn(acc[mt][nt][0] + b0, acc[mt][nt][1] + b1);
            *(__half2*)(Op + (size_t)(r + 8) * DHEAD + c) =
                __floats2half2_rn(acc[mt][nt][2] + b0, acc[mt][nt][3] + b1);
        }
    }
}

// ===========================================================================
// Scores on fp16 tensor cores (NT) + fp32 exp; writes fp16 e + colsum.
// ===========================================================================
#define SC_STR 136
#define SC_SMEM (2 * 128 * SC_STR * 2)

__global__ void __launch_bounds__(256, 2)
scores_f16_kernel(float scale)
{
    extern __shared__ __half scs[];
    const uint32_t sA = (uint32_t)__cvta_generic_to_shared(scs);
    const uint32_t sB = sA + 128 * SC_STR * 2;
    __shared__ float red[16][128];

    const int tid  = threadIdx.x;
    const int lane = tid & 31;
    const int wid  = tid >> 5;
    const int wm   = wid >> 2;
    const int wn   = wid & 3;
    const int z    = blockIdx.z;
    const int m0   = blockIdx.y * 128;
    const int n0   = blockIdx.x * 128;

    const __half* Ap = g_Sh + (size_t)z * NSENT * DHEAD + (size_t)m0 * DHEAD;
    const __half* Bp = g_Kh + (size_t)z * NKNOW * DHEAD + (size_t)n0 * DHEAD;

    {
        const int r  = tid >> 1;
        const int c0 = (tid & 1) << 6;
#pragma unroll
        for (int i = 0; i < 8; i++) {
            cp_async16(sA + (uint32_t)(r * SC_STR + c0 + 8 * i) * 2,
                       Ap + (size_t)r * DHEAD + c0 + 8 * i);
            cp_async16(sB + (uint32_t)(r * SC_STR + c0 + 8 * i) * 2,
                       Bp + (size_t)r * DHEAD + c0 + 8 * i);
        }
        asm volatile("cp.async.commit_group;" ::: "memory");
        asm volatile("cp.async.wait_group 0;" ::: "memory");
        __syncthreads();
    }

    float acc[4][4][4];
#pragma unroll
    for (int mt = 0; mt < 4; mt++)
#pragma unroll
        for (int nt = 0; nt < 4; nt++)
#pragma unroll
            for (int r = 0; r < 4; r++) acc[mt][nt][r] = 0.f;

#pragma unroll
    for (int ks = 0; ks < 8; ks++) {
        uint32_t bf[4][2];
#pragma unroll
        for (int ntp = 0; ntp < 2; ntp++) {
            uint32_t r[4];
            uint32_t addr = sB + (uint32_t)(((wn * 32 + ntp * 16 + (lane & 15)) * SC_STR
                           + ks * 16 + ((lane >> 4) << 3)) * 2);
            ldsm_x4(r, addr);
            bf[2 * ntp][0]     = r[0];
            bf[2 * ntp][1]     = r[2];
            bf[2 * ntp + 1][0] = r[1];
            bf[2 * ntp + 1][1] = r[3];
        }
#pragma unroll
        for (int mt = 0; mt < 4; mt++) {
            uint32_t af[4];
            uint32_t addr = sA + (uint32_t)(((wm * 64 + mt * 16 + (lane & 15)) * SC_STR
                           + ks * 16 + ((lane >> 4) << 3)) * 2);
            ldsm_x4(af, addr);
#pragma unroll
            for (int nt = 0; nt < 4; nt++)
                mma_f16(acc[mt][nt], af, bf[nt]);
        }
    }

    float cp[8];
#pragma unroll
    for (int j = 0; j < 8; j++) cp[j] = 0.f;
    __half* Ep = g_Ah + (size_t)z * NSENT * NKNOW;
#pragma unroll
    for (int mt = 0; mt < 4; mt++) {
        const int r = m0 + wm * 64 + mt * 16 + (lane >> 2);
#pragma unroll
        for (int nt = 0; nt < 4; nt++) {
            const int c = n0 + wn * 32 + nt * 8 + ((lane & 3) << 1);
            float e0 = __expf(acc[mt][nt][0] * scale);
            float e1 = __expf(acc[mt][nt][1] * scale);
            float e2 = __expf(acc[mt][nt][2] * scale);
            float e3 = __expf(acc[mt][nt][3] * scale);
            *(__half2*)(Ep + (size_t)r * NKNOW + c)       = __floats2half2_rn(e0, e1);
            *(__half2*)(Ep + (size_t)(r + 8) * NKNOW + c) = __floats2half2_rn(e2, e3);
            cp[nt * 2]     += e0 + e2;
            cp[nt * 2 + 1] += e1 + e3;
        }
    }
    const int rr = wm * 8 + (lane >> 2);
#pragma unroll
    for (int nt = 0; nt < 4; nt++) {
        red[rr][wn * 32 + nt * 8 + ((lane & 3) << 1)]     = cp[nt * 2];
        red[rr][wn * 32 + nt * 8 + ((lane & 3) << 1) + 1] = cp[nt * 2 + 1];
    }
    __syncthreads();
    if (tid < 128) {
        float s = 0.f;
#pragma unroll
        for (int r = 0; r < 16; r++) s += red[r][tid];
        atomicAdd(&g_colsum[(size_t)z * NKNOW + n0 + tid], s);
    }
}

// ===========================================================================
// inv kernel: g_invh = fp16(1/colsum)
// ===========================================================================
__global__ __launch_bounds__(256)
void inv_kernel()
{
    int i = blockIdx.x * 256 + threadIdx.x;
    g_invh[i] = __float2half_rn(1.f / g_colsum[i]);
}

// ===========================================================================
// Normalize: attn fp32 = e * (1/colsum).  (no fp16 rewrite — fused kernel
// scales fragments by g_invh in-register.)
// ===========================================================================
__global__ __launch_bounds__(256)
void normalize_kernel(float* __restrict__ attn)
{
    const int h = blockIdx.z;
    const int m = (blockIdx.x * 256 + threadIdx.x) * 2;
    const int n0 = blockIdx.y * 64;
    float2 cs = *(const float2*)&g_colsum[(size_t)h * NKNOW + m];
    const float iv0 = 1.f / cs.x, iv1 = 1.f / cs.y;
    const size_t base = (size_t)h * NSENT * NKNOW + (size_t)n0 * NKNOW + m;
    float*  p   = attn + base;
    const __half* p16 = g_Ah + base;
#pragma unroll 4
    for (int nn = 0; nn < 64; nn++) {
        size_t idx = (size_t)nn * NKNOW;
        __half2 e = *(const __half2*)(p16 + idx);
        *(float2*)(p + idx) = make_float2(__half2float(__low2half(e))  * iv0,
                                          __half2float(__high2half(e)) * iv1);
    }
}

// ===========================================================================
// fused = (e .* inv) @ knowledge  (fp16 mma, fp32 accum, in-register scaling)
//   R9 config: CTA 128x256xK64, 512 thr (16 warps 4x4, warp 32x64), 3-stage
// ===========================================================================
#define FBM 128
#define FBN 256
#define FBK 64
#define FSTG 3
#define SA_STR 72
#define SB_STR 264
#define SA_H (FBM * SA_STR)                 // 9216 halves/stage
#define SB_H (FBK * SB_STR)                 // 16896 halves/stage
#define FSMEM (FSTG * (SA_H + SB_H) * 2)    // 156672 B

__global__ void __launch_bounds__(512, 1)
fused_mma_f16(float* __restrict__ C)
{
    extern __shared__ __half smh[];
    const uint32_t sA_u32 = (uint32_t)__cvta_generic_to_shared(smh);
    const uint32_t sB_u32 = sA_u32 + FSTG * SA_H * 2;

    const int tid  = threadIdx.x;
    const int lane = tid & 31;
    const int wid  = tid >> 5;
    const int wm   = wid & 3;
    const int wn   = wid >> 2;
    const int z    = blockIdx.z;
    const int m0   = blockIdx.y * FBM;
    const int n0   = blockIdx.x * FBN;

    const __half* Ap = g_Ah + (size_t)z * NSENT * NKNOW + (size_t)m0 * NKNOW;
    const __half* Bp = g_Bh + n0;
    const __half* invp = g_invh + (size_t)z * NKNOW;

    const int a_row  = tid >> 2;            // 0..127
    const int a_ch   = (tid & 3) << 3;      // 0..24
    const int b_row0 = tid >> 5;            // 0..15
    const int b_ch0  = (tid & 31) << 3;     // 0..248

    float acc[2][8][4];
#pragma unroll
    for (int mt = 0; mt < 2; mt++)
#pragma unroll
        for (int nt = 0; nt < 8; nt++)
#pragma unroll
            for (int r = 0; r < 4; r++) acc[mt][nt][r] = 0.f;

    const int NT = NKNOW / FBK;             // 128

    auto issue = [&](int kt, int s) {
        const __half* abase = Ap + (size_t)kt * FBK;
#pragma unroll
        for (int i = 0; i < 2; i++)
            cp_async16(sA_u32 + (uint32_t)(s * SA_H + a_row * SA_STR + a_ch + 32 * i) * 2,
                       abase + (size_t)a_row * NKNOW + a_ch + 32 * i);
        const __half* bbase = Bp + (size_t)(kt * FBK) * KFDIM;
#pragma unroll
        for (int p = 0; p < 4; p++) {
            int row = b_row0 + p * 16;
            cp_async16(sB_u32 + (uint32_t)(s * SB_H + row * SB_STR + b_ch0) * 2,
                       bbase + (size_t)row * KFDIM + b_ch0);
        }
        asm volatile("cp.async.commit_group;" ::: "memory");
    };

    issue(0, 0); issue(1, 1);

    int scur = 0;
    for (int kt = 0; kt < NT; kt++) {
        if (kt + 1 < NT) asm volatile("cp.async.wait_group 1;" ::: "memory");
        else             asm volatile("cp.async.wait_group 0;" ::: "memory");
        __syncthreads();

        if (kt + 2 < NT) {
            int snx = scur + 2; if (snx >= FSTG) snx -= FSTG;
            issue(kt + 2, snx);
        }

        const uint32_t aBase = sA_u32 + (uint32_t)(scur * SA_H) * 2;
        const uint32_t bBase = sB_u32 + (uint32_t)(scur * SB_H) * 2;
        const __half2* ivb = (const __half2*)(invp + (size_t)kt * FBK);

#pragma unroll
        for (int ks = 0; ks < 4; ks++) {
            // inv pairs: A regs a0/a1 cover k=2c,2c+1 (iv0); a2/a3 cover k+8 (iv1)
            uint32_t iv0 = *(const uint32_t*)(ivb + ks * 8 + (lane & 3));
            uint32_t iv1 = *(const uint32_t*)(ivb + ks * 8 + 4 + (lane & 3));

            uint32_t bf[8][2];
#pragma unroll
            for (int ntp = 0; ntp < 4; ntp++) {
                uint32_t r[4];
                uint32_t addr = bBase + (uint32_t)(((ks * 16 + (lane & 15)) * SB_STR
                               + wn * 64 + ntp * 16 + ((lane >> 4) << 3)) * 2);
                ldsm_x4_t(r, addr);
                bf[2 * ntp][0]     = r[0];
                bf[2 * ntp][1]     = r[1];
                bf[2 * ntp + 1][0] = r[2];
                bf[2 * ntp + 1][1] = r[3];
            }
#pragma unroll
            for (int mt = 0; mt < 2; mt++) {
                uint32_t af[4];
                uint32_t addr = aBase + (uint32_t)(((wm * 32 + mt * 16 + (lane & 15)) * SA_STR
                               + ks * 16 + ((lane >> 4) << 3)) * 2);
                ldsm_x4(af, addr);
                af[0] = hmul2u(af[0], iv0);
                af[1] = hmul2u(af[1], iv0);
                af[2] = hmul2u(af[2], iv1);
                af[3] = hmul2u(af[3], iv1);
#pragma unroll
                for (int nt = 0; nt < 8; nt++)
                    mma_f16(acc[mt][nt], af, bf[nt]);
            }
        }
        scur++; if (scur >= FSTG) scur -= FSTG;
    }

    const int ldc = NHEADS * KFDIM;
#pragma unroll
    for (int mt = 0; mt < 2; mt++) {
        const int r = m0 + wm * 32 + mt * 16 + (lane >> 2);
#pragma unroll
        for (int nt = 0; nt < 8; nt++) {
            const int c = z * KFDIM + n0 + wn * 64 + nt * 8 + ((lane & 3) << 1);
            *(float2*)(C + (size_t)r * ldc + c)       = make_float2(acc[mt][nt][0], acc[mt][nt][1]);
            *(float2*)(C + (size_t)(r + 8) * ldc + c) = make_float2(acc[mt][nt][2], acc[mt][nt][3]);
        }
    }
}

// ===========================================================================
// Host side
// ===========================================================================
extern "C" void kernel_launch(void* const* d_in, const int* in_sizes, int n_in,
                              void* d_out, int out_size)
{
    const float* sentences = (const float*)d_in[0];
    const float* knowledge = (const float*)d_in[1];
    const float* w_s       = (const float*)d_in[2];
    const float* b_s       = (const float*)d_in[3];
    const float* w_k       = (const float*)d_in[4];
    const float* b_k       = (const float*)d_in[5];

    float* attn  = (float*)d_out;
    float* fused = (float*)d_out + (size_t)NHEADS * NSENT * NKNOW;

    float* csum = nullptr;
    __half *snth = nullptr, *wsh = nullptr, *Sh = nullptr, *Kh = nullptr,
           *wkh = nullptr, *Bh = nullptr;
    cudaGetSymbolAddress((void**)&csum, g_colsum);
    cudaGetSymbolAddress((void**)&snth, g_snth);
    cudaGetSymbolAddress((void**)&wsh,  g_wsh);
    cudaGetSymbolAddress((void**)&Sh,   g_Sh);
    cudaGetSymbolAddress((void**)&Kh,   g_Kh);
    cudaGetSymbolAddress((void**)&wkh,  g_wkh);
    cudaGetSymbolAddress((void**)&Bh,   g_Bh);

    static bool attrs_set = false;
    if (!attrs_set) {
        cudaFuncSetAttribute(proj_f16_merged,
                             cudaFuncAttributeMaxDynamicSharedMemorySize, KPSMEM);
        cudaFuncSetAttribute(scores_f16_kernel,
                             cudaFuncAttributeMaxDynamicSharedMemorySize, SC_SMEM);
        cudaFuncSetAttribute(fused_mma_f16,
                             cudaFuncAttributeMaxDynamicSharedMemorySize, FSMEM);
        attrs_set = true;
    }

    // 0) zero colsums; fp16 conversions
    cudaMemsetAsync(csum, 0, (size_t)NHEADS * NKNOW * sizeof(float));
    cvt_f16_kernel<<<((size_t)NKNOW * KFDIM) / 1024, 256>>>(knowledge, Bh);
    cvt_f16_kernel<<<((size_t)NHEADS * KFDIM * DHEAD) / 1024, 256>>>(w_k, wkh);
    cvt_f16_kernel<<<((size_t)NSENT * DMODEL) / 1024, 256>>>(sentences, snth);
    cvt_f16_kernel<<<((size_t)NHEADS * DMODEL * DHEAD) / 1024, 256>>>(w_s, wsh);

    // 1+2) merged S & K projections (fp16 mma)
    {
        dim3 grid(1, NKNOW / 128, 2 * NHEADS);
        proj_f16_merged<<<grid, 256, KPSMEM>>>(Bh, wkh, b_k, Kh,
                                               snth, wsh, b_s, Sh);
    }
    // 3) scores + exp -> fp16 e + colsum
    {
        dim3 grid(NKNOW / 128, NSENT / 128, NHEADS);
        scores_f16_kernel<<<grid, 256, SC_SMEM>>>(0.08838834764831845f);
    }
    // 4) inv + normalize (fp32 attn output only)
    inv_kernel<<<(NHEADS * NKNOW) / 256, 256>>>();
    {
        dim3 grid(NKNOW / 512, NSENT / 64, NHEADS);
        normalize_kernel<<<grid, 256>>>(attn);
    }
    // 5) fused GEMM (R9 config + in-register inv scaling)
    {
        dim3 grid(KFDIM / FBN, NSENT / FBM, NHEADS);
        fused_mma_f16<<<grid, 512, FSMEM>>>(fused);
    }
}

// round 13
// speedup vs baseline: 1.3122x; 1.1143x over previous
#include <cuda_runtime.h>
#include <cuda_fp16.h>
#include <math.h>
#include <stdint.h>

#define NHEADS 8
#define DMODEL 1024
#define DHEAD  128
#define KFDIM  3072
#define NSENT  2048
#define NKNOW  8192

// Scratch (no cudaMalloc allowed).
__device__ __half g_snth[NSENT * DMODEL];               // 4 MB  sentences fp16
__device__ __half g_wsh[NHEADS * DMODEL * DHEAD];       // 2 MB  w_s fp16
__device__ __half g_Sh[NHEADS * NSENT * DHEAD];         // 4 MB  S fp16
__device__ __half g_Kh[NHEADS * NKNOW * DHEAD];         // 16 MB K fp16
__device__ __half g_wkh[NHEADS * KFDIM * DHEAD];        // 6 MB  w_k fp16
__device__ float  g_colsum[NHEADS * NKNOW];             // 256 KB
__device__ __half g_Ah[(size_t)NHEADS * NSENT * NKNOW]; // 268 MB e fp16
__device__ __half g_An[(size_t)NHEADS * NSENT * NKNOW]; // 268 MB normalized fp16
__device__ __half g_Bh[(size_t)NKNOW * KFDIM];          // 50 MB knowledge fp16

// ===========================================================================
// helpers
// ===========================================================================
__device__ __forceinline__ void mma_f16(float* d, const uint32_t* a, const uint32_t* b) {
    asm volatile(
        "mma.sync.aligned.m16n8k16.row.col.f32.f16.f16.f32 "
        "{%0,%1,%2,%3}, {%4,%5,%6,%7}, {%8,%9}, {%0,%1,%2,%3};"
        : "+f"(d[0]), "+f"(d[1]), "+f"(d[2]), "+f"(d[3])
        : "r"(a[0]), "r"(a[1]), "r"(a[2]), "r"(a[3]), "r"(b[0]), "r"(b[1]));
}
__device__ __forceinline__ void cp_async16(uint32_t dst, const void* src) {
    asm volatile("cp.async.cg.shared.global [%0], [%1], 16;" :: "r"(dst), "l"(src));
}
__device__ __forceinline__ void ldsm_x4(uint32_t* r, uint32_t addr) {
    asm volatile("ldmatrix.sync.aligned.m8n8.x4.shared.b16 {%0,%1,%2,%3}, [%4];"
                 : "=r"(r[0]), "=r"(r[1]), "=r"(r[2]), "=r"(r[3]) : "r"(addr));
}
__device__ __forceinline__ void ldsm_x4_t(uint32_t* r, uint32_t addr) {
    asm volatile("ldmatrix.sync.aligned.m8n8.x4.trans.shared.b16 {%0,%1,%2,%3}, [%4];"
                 : "=r"(r[0]), "=r"(r[1]), "=r"(r[2]), "=r"(r[3]) : "r"(addr));
}

// fp32 -> fp16 (rn)
__global__ __launch_bounds__(256)
void cvt_f16_kernel(const float* __restrict__ in, __half* __restrict__ out)
{
    size_t i = ((size_t)blockIdx.x * 256 + threadIdx.x) * 4;
    float4 v = *(const float4*)(in + i);
    *(__half2*)(out + i)     = __floats2half2_rn(v.x, v.y);
    *(__half2*)(out + i + 2) = __floats2half2_rn(v.z, v.w);
}

// ===========================================================================
// Generic per-head projection on fp16 tensor cores (R9 version):
//   out[z][m][n] = f16( A[m,:] @ W[z][:,n] + bias[z][n] ),  n < 128
// ===========================================================================
#define KP_STG 4
#define KPA_STR 40
#define KPB_STR 136
#define KPA_H (128 * KPA_STR)
#define KPB_H (32 * KPB_STR)
#define KPSMEM (KP_STG * (KPA_H + KPB_H) * 2)   // 75776 B

__global__ void __launch_bounds__(256, 2)
proj_f16_kernel(const __half* __restrict__ A, const __half* __restrict__ W,
                const float* __restrict__ bias, __half* __restrict__ out,
                int Kdim, int Mtot)
{
    extern __shared__ __half kps[];
    const uint32_t sA = (uint32_t)__cvta_generic_to_shared(kps);
    const uint32_t sB = sA + KP_STG * KPA_H * 2;

    const int tid  = threadIdx.x;
    const int lane = tid & 31;
    const int wid  = tid >> 5;
    const int wm   = wid >> 2;
    const int wn   = wid & 3;
    const int z    = blockIdx.z;
    const int m0   = blockIdx.y * 128;

    const __half* Ap = A + (size_t)m0 * Kdim;
    const __half* Bp = W + (size_t)z * Kdim * DHEAD;

    const int a_r = tid >> 1;
    const int a_c = (tid & 1) << 4;
    const int b_r = tid >> 3;
    const int b_c = (tid & 7) << 4;

    float acc[4][4][4];
#pragma unroll
    for (int mt = 0; mt < 4; mt++)
#pragma unroll
        for (int nt = 0; nt < 4; nt++)
#pragma unroll
            for (int r = 0; r < 4; r++) acc[mt][nt][r] = 0.f;

    const int NT = Kdim / 32;

    auto issue = [&](int kt, int s) {
#pragma unroll
        for (int i = 0; i < 2; i++)
            cp_async16(sA + (uint32_t)(s * KPA_H + a_r * KPA_STR + a_c + 8 * i) * 2,
                       Ap + (size_t)a_r * Kdim + kt * 32 + a_c + 8 * i);
#pragma unroll
        for (int i = 0; i < 2; i++)
            cp_async16(sB + (uint32_t)(s * KPB_H + b_r * KPB_STR + b_c + 8 * i) * 2,
                       Bp + (size_t)(kt * 32 + b_r) * DHEAD + b_c + 8 * i);
        asm volatile("cp.async.commit_group;" ::: "memory");
    };

    issue(0, 0); issue(1, 1); issue(2, 2);

    int scur = 0;
    for (int kt = 0; kt < NT; kt++) {
        if (kt < NT - 2)       asm volatile("cp.async.wait_group 2;" ::: "memory");
        else if (kt == NT - 2) asm volatile("cp.async.wait_group 1;" ::: "memory");
        else                   asm volatile("cp.async.wait_group 0;" ::: "memory");
        __syncthreads();

        if (kt + 3 < NT) {
            int snx = scur + 3; if (snx >= KP_STG) snx -= KP_STG;
            issue(kt + 3, snx);
        }

        const uint32_t aB = sA + (uint32_t)(scur * KPA_H) * 2;
        const uint32_t bB = sB + (uint32_t)(scur * KPB_H) * 2;

#pragma unroll
        for (int ks = 0; ks < 2; ks++) {
            uint32_t bf[4][2];
#pragma unroll
            for (int ntp = 0; ntp < 2; ntp++) {
                uint32_t r[4];
                uint32_t addr = bB + (uint32_t)(((ks * 16 + (lane & 15)) * KPB_STR
                               + wn * 32 + ntp * 16 + ((lane >> 4) << 3)) * 2);
                ldsm_x4_t(r, addr);
                bf[2 * ntp][0]     = r[0];
                bf[2 * ntp][1]     = r[1];
                bf[2 * ntp + 1][0] = r[2];
                bf[2 * ntp + 1][1] = r[3];
            }
#pragma unroll
            for (int mt = 0; mt < 4; mt++) {
                uint32_t af[4];
                uint32_t addr = aB + (uint32_t)(((wm * 64 + mt * 16 + (lane & 15)) * KPA_STR
                               + ks * 16 + ((lane >> 4) << 3)) * 2);
                ldsm_x4(af, addr);
#pragma unroll
                for (int nt = 0; nt < 4; nt++)
                    mma_f16(acc[mt][nt], af, bf[nt]);
            }
        }
        scur++; if (scur >= KP_STG) scur -= KP_STG;
        __syncthreads();
    }

    __half* Op = out + (size_t)z * Mtot * DHEAD;
#pragma unroll
    for (int mt = 0; mt < 4; mt++) {
        const int r = m0 + wm * 64 + mt * 16 + (lane >> 2);
#pragma unroll
        for (int nt = 0; nt < 4; nt++) {
            const int c = wn * 32 + nt * 8 + ((lane & 3) << 1);
            float b0 = bias[z * DHEAD + c], b1 = bias[z * DHEAD + c + 1];
            *(__half2*)(Op + (size_t)r * DHEAD + c) =
                __floats2half2_rn(acc[mt][nt][0] + b0, acc[mt][nt][1] + b1);
            *(__half2*)(Op + (size_t)(r + 8) * DHEAD + c) =
                __floats2half2_rn(acc[mt][nt][2] + b0, acc[mt][nt][3] + b1);
        }
    }
}

// ===========================================================================
// Scores on fp16 tensor cores (NT) + fp32 exp; writes fp16 e + colsum.
// ===========================================================================
#define SC_STR 136
#define SC_SMEM (2 * 128 * SC_STR * 2)

__global__ void __launch_bounds__(256, 2)
scores_f16_kernel(float scale)
{
    extern __shared__ __half scs[];
    const uint32_t sA = (uint32_t)__cvta_generic_to_shared(scs);
    const uint32_t sB = sA + 128 * SC_STR * 2;
    __shared__ float red[16][128];

    const int tid  = threadIdx.x;
    const int lane = tid & 31;
    const int wid  = tid >> 5;
    const int wm   = wid >> 2;
    const int wn   = wid & 3;
    const int z    = blockIdx.z;
    const int m0   = blockIdx.y * 128;
    const int n0   = blockIdx.x * 128;

    const __half* Ap = g_Sh + (size_t)z * NSENT * DHEAD + (size_t)m0 * DHEAD;
    const __half* Bp = g_Kh + (size_t)z * NKNOW * DHEAD + (size_t)n0 * DHEAD;

    {
        const int r  = tid >> 1;
        const int c0 = (tid & 1) << 6;
#pragma unroll
        for (int i = 0; i < 8; i++) {
            cp_async16(sA + (uint32_t)(r * SC_STR + c0 + 8 * i) * 2,
                       Ap + (size_t)r * DHEAD + c0 + 8 * i);
            cp_async16(sB + (uint32_t)(r * SC_STR + c0 + 8 * i) * 2,
                       Bp + (size_t)r * DHEAD + c0 + 8 * i);
        }
        asm volatile("cp.async.commit_group;" ::: "memory");
        asm volatile("cp.async.wait_group 0;" ::: "memory");
        __syncthreads();
    }

    float acc[4][4][4];
#pragma unroll
    for (int mt = 0; mt < 4; mt++)
#pragma unroll
        for (int nt = 0; nt < 4; nt++)
#pragma unroll
            for (int r = 0; r < 4; r++) acc[mt][nt][r] = 0.f;

#pragma unroll
    for (int ks = 0; ks < 8; ks++) {
        uint32_t bf[4][2];
#pragma unroll
        for (int ntp = 0; ntp < 2; ntp++) {
            uint32_t r[4];
            uint32_t addr = sB + (uint32_t)(((wn * 32 + ntp * 16 + (lane & 15)) * SC_STR
                           + ks * 16 + ((lane >> 4) << 3)) * 2);
            ldsm_x4(r, addr);
            bf[2 * ntp][0]     = r[0];
            bf[2 * ntp][1]     = r[2];
            bf[2 * ntp + 1][0] = r[1];
            bf[2 * ntp + 1][1] = r[3];
        }
#pragma unroll
        for (int mt = 0; mt < 4; mt++) {
            uint32_t af[4];
            uint32_t addr = sA + (uint32_t)(((wm * 64 + mt * 16 + (lane & 15)) * SC_STR
                           + ks * 16 + ((lane >> 4) << 3)) * 2);
            ldsm_x4(af, addr);
#pragma unroll
            for (int nt = 0; nt < 4; nt++)
                mma_f16(acc[mt][nt], af, bf[nt]);
        }
    }

    float cp[8];
#pragma unroll
    for (int j = 0; j < 8; j++) cp[j] = 0.f;
    __half* Ep = g_Ah + (size_t)z * NSENT * NKNOW;
#pragma unroll
    for (int mt = 0; mt < 4; mt++) {
        const int r = m0 + wm * 64 + mt * 16 + (lane >> 2);
#pragma unroll
        for (int nt = 0; nt < 4; nt++) {
            const int c = n0 + wn * 32 + nt * 8 + ((lane & 3) << 1);
            float e0 = __expf(acc[mt][nt][0] * scale);
            float e1 = __expf(acc[mt][nt][1] * scale);
            float e2 = __expf(acc[mt][nt][2] * scale);
            float e3 = __expf(acc[mt][nt][3] * scale);
            *(__half2*)(Ep + (size_t)r * NKNOW + c)       = __floats2half2_rn(e0, e1);
            *(__half2*)(Ep + (size_t)(r + 8) * NKNOW + c) = __floats2half2_rn(e2, e3);
            cp[nt * 2]     += e0 + e2;
            cp[nt * 2 + 1] += e1 + e3;
        }
    }
    const int rr = wm * 8 + (lane >> 2);
#pragma unroll
    for (int nt = 0; nt < 4; nt++) {
        red[rr][wn * 32 + nt * 8 + ((lane & 3) << 1)]     = cp[nt * 2];
        red[rr][wn * 32 + nt * 8 + ((lane & 3) << 1) + 1] = cp[nt * 2 + 1];
    }
    __syncthreads();
    if (tid < 128) {
        float s = 0.f;
#pragma unroll
        for (int r = 0; r < 16; r++) s += red[r][tid];
        atomicAdd(&g_colsum[(size_t)z * NKNOW + n0 + tid], s);
    }
}

// ===========================================================================
// normalize_a: g_An = f16( e * 1/colsum )  — feeds the fused GEMM
// ===========================================================================
__global__ __launch_bounds__(256)
void normalize_a_kernel()
{
    const int h = blockIdx.z;
    const int m = (blockIdx.x * 256 + threadIdx.x) * 2;
    const int n0 = blockIdx.y * 64;
    float2 cs = *(const float2*)&g_colsum[(size_t)h * NKNOW + m];
    const float iv0 = 1.f / cs.x, iv1 = 1.f / cs.y;
    const size_t base = (size_t)h * NSENT * NKNOW + (size_t)n0 * NKNOW + m;
    const __half* pe = g_Ah + base;
    __half*       pn = g_An + base;
#pragma unroll 4
    for (int nn = 0; nn < 64; nn++) {
        size_t idx = (size_t)nn * NKNOW;
        __half2 e = *(const __half2*)(pe + idx);
        *(__half2*)(pn + idx) = __floats2half2_rn(__half2float(__low2half(e))  * iv0,
                                                  __half2float(__high2half(e)) * iv1);
    }
}

// ===========================================================================
// normalize_b: attn fp32 = e * 1/colsum  — independent of fused (parallel)
// ===========================================================================
__global__ __launch_bounds__(256)
void normalize_b_kernel(float* __restrict__ attn)
{
    const int h = blockIdx.z;
    const int m = (blockIdx.x * 256 + threadIdx.x) * 2;
    const int n0 = blockIdx.y * 64;
    float2 cs = *(const float2*)&g_colsum[(size_t)h * NKNOW + m];
    const float iv0 = 1.f / cs.x, iv1 = 1.f / cs.y;
    const size_t base = (size_t)h * NSENT * NKNOW + (size_t)n0 * NKNOW + m;
    const __half* pe = g_Ah + base;
    float*        p  = attn + base;
#pragma unroll 4
    for (int nn = 0; nn < 64; nn++) {
        size_t idx = (size_t)nn * NKNOW;
        __half2 e = *(const __half2*)(pe + idx);
        *(float2*)(p + idx) = make_float2(__half2float(__low2half(e))  * iv0,
                                          __half2float(__high2half(e)) * iv1);
    }
}

// ===========================================================================
// fused = attn_norm_h16 @ knowledge_h16 (fp16 mma, fp32 accum) — R9 config
//   CTA 128x256xK64, 512 thr (16 warps 4x4, warp 32x64), 3-stage cp.async
// ===========================================================================
#define FBM 128
#define FBN 256
#define FBK 64
#define FSTG 3
#define SA_STR 72
#define SB_STR 264
#define SA_H (FBM * SA_STR)
#define SB_H (FBK * SB_STR)
#define FSMEM (FSTG * (SA_H + SB_H) * 2)    // 156672 B

__global__ void __launch_bounds__(512, 1)
fused_mma_f16(float* __restrict__ C)
{
    extern __shared__ __half smh[];
    const uint32_t sA_u32 = (uint32_t)__cvta_generic_to_shared(smh);
    const uint32_t sB_u32 = sA_u32 + FSTG * SA_H * 2;

    const int tid  = threadIdx.x;
    const int lane = tid & 31;
    const int wid  = tid >> 5;
    const int wm   = wid & 3;
    const int wn   = wid >> 2;
    const int z    = blockIdx.z;
    const int m0   = blockIdx.y * FBM;
    const int n0   = blockIdx.x * FBN;

    const __half* Ap = g_An + (size_t)z * NSENT * NKNOW + (size_t)m0 * NKNOW;
    const __half* Bp = g_Bh + n0;

    const int a_row  = tid >> 2;
    const int a_ch   = (tid & 3) << 3;
    const int b_row0 = tid >> 5;
    const int b_ch0  = (tid & 31) << 3;

    float acc[2][8][4];
#pragma unroll
    for (int mt = 0; mt < 2; mt++)
#pragma unroll
        for (int nt = 0; nt < 8; nt++)
#pragma unroll
            for (int r = 0; r < 4; r++) acc[mt][nt][r] = 0.f;

    const int NT = NKNOW / FBK;             // 128

    auto issue = [&](int kt, int s) {
        const __half* abase = Ap + (size_t)kt * FBK;
#pragma unroll
        for (int i = 0; i < 2; i++)
            cp_async16(sA_u32 + (uint32_t)(s * SA_H + a_row * SA_STR + a_ch + 32 * i) * 2,
                       abase + (size_t)a_row * NKNOW + a_ch + 32 * i);
        const __half* bbase = Bp + (size_t)(kt * FBK) * KFDIM;
#pragma unroll
        for (int p = 0; p < 4; p++) {
            int row = b_row0 + p * 16;
            cp_async16(sB_u32 + (uint32_t)(s * SB_H + row * SB_STR + b_ch0) * 2,
                       bbase + (size_t)row * KFDIM + b_ch0);
        }
        asm volatile("cp.async.commit_group;" ::: "memory");
    };

    issue(0, 0); issue(1, 1);

    int scur = 0;
    for (int kt = 0; kt < NT; kt++) {
        if (kt + 1 < NT) asm volatile("cp.async.wait_group 1;" ::: "memory");
        else             asm volatile("cp.async.wait_group 0;" ::: "memory");
        __syncthreads();

        if (kt + 2 < NT) {
            int snx = scur + 2; if (snx >= FSTG) snx -= FSTG;
            issue(kt + 2, snx);
        }

        const uint32_t aBase = sA_u32 + (uint32_t)(scur * SA_H) * 2;
        const uint32_t bBase = sB_u32 + (uint32_t)(scur * SB_H) * 2;

#pragma unroll
        for (int ks = 0; ks < 4; ks++) {
            uint32_t bf[8][2];
#pragma unroll
            for (int ntp = 0; ntp < 4; ntp++) {
                uint32_t r[4];
                uint32_t addr = bBase + (uint32_t)(((ks * 16 + (lane & 15)) * SB_STR
                               + wn * 64 + ntp * 16 + ((lane >> 4) << 3)) * 2);
                ldsm_x4_t(r, addr);
                bf[2 * ntp][0]     = r[0];
                bf[2 * ntp][1]     = r[1];
                bf[2 * ntp + 1][0] = r[2];
                bf[2 * ntp + 1][1] = r[3];
            }
#pragma unroll
            for (int mt = 0; mt < 2; mt++) {
                uint32_t af[4];
                uint32_t addr = aBase + (uint32_t)(((wm * 32 + mt * 16 + (lane & 15)) * SA_STR
                               + ks * 16 + ((lane >> 4) << 3)) * 2);
                ldsm_x4(af, addr);
#pragma unroll
                for (int nt = 0; nt < 8; nt++)
                    mma_f16(acc[mt][nt], af, bf[nt]);
            }
        }
        scur++; if (scur >= FSTG) scur -= FSTG;
    }

    const int ldc = NHEADS * KFDIM;
#pragma unroll
    for (int mt = 0; mt < 2; mt++) {
        const int r = m0 + wm * 32 + mt * 16 + (lane >> 2);
#pragma unroll
        for (int nt = 0; nt < 8; nt++) {
            const int c = z * KFDIM + n0 + wn * 64 + nt * 8 + ((lane & 3) << 1);
            *(float2*)(C + (size_t)r * ldc + c)       = make_float2(acc[mt][nt][0], acc[mt][nt][1]);
            *(float2*)(C + (size_t)(r + 8) * ldc + c) = make_float2(acc[mt][nt][2], acc[mt][nt][3]);
        }
    }
}

// ===========================================================================
// Host side
// ===========================================================================
extern "C" void kernel_launch(void* const* d_in, const int* in_sizes, int n_in,
                              void* d_out, int out_size)
{
    const float* sentences = (const float*)d_in[0];
    const float* knowledge = (const float*)d_in[1];
    const float* w_s       = (const float*)d_in[2];
    const float* b_s       = (const float*)d_in[3];
    const float* w_k       = (const float*)d_in[4];
    const float* b_k       = (const float*)d_in[5];

    float* attn  = (float*)d_out;
    float* fused = (float*)d_out + (size_t)NHEADS * NSENT * NKNOW;

    float* csum = nullptr;
    __half *snth = nullptr, *wsh = nullptr, *Sh = nullptr, *Kh = nullptr,
           *wkh = nullptr, *Bh = nullptr;
    cudaGetSymbolAddress((void**)&csum, g_colsum);
    cudaGetSymbolAddress((void**)&snth, g_snth);
    cudaGetSymbolAddress((void**)&wsh,  g_wsh);
    cudaGetSymbolAddress((void**)&Sh,   g_Sh);
    cudaGetSymbolAddress((void**)&Kh,   g_Kh);
    cudaGetSymbolAddress((void**)&wkh,  g_wkh);
    cudaGetSymbolAddress((void**)&Bh,   g_Bh);

    static cudaStream_t s2;
    static cudaEvent_t evFork, evJoin;
    static bool init_done = false;
    if (!init_done) {
        cudaFuncSetAttribute(proj_f16_kernel,
                             cudaFuncAttributeMaxDynamicSharedMemorySize, KPSMEM);
        cudaFuncSetAttribute(scores_f16_kernel,
                             cudaFuncAttributeMaxDynamicSharedMemorySize, SC_SMEM);
        cudaFuncSetAttribute(fused_mma_f16,
                             cudaFuncAttributeMaxDynamicSharedMemorySize, FSMEM);
        cudaStreamCreateWithFlags(&s2, cudaStreamNonBlocking);
        cudaEventCreateWithFlags(&evFork, cudaEventDisableTiming);
        cudaEventCreateWithFlags(&evJoin, cudaEventDisableTiming);
        init_done = true;
    }

    // 0) zero colsums; fp16 conversions
    cudaMemsetAsync(csum, 0, (size_t)NHEADS * NKNOW * sizeof(float));
    cvt_f16_kernel<<<((size_t)NKNOW * KFDIM) / 1024, 256>>>(knowledge, Bh);
    cvt_f16_kernel<<<((size_t)NHEADS * KFDIM * DHEAD) / 1024, 256>>>(w_k, wkh);
    cvt_f16_kernel<<<((size_t)NSENT * DMODEL) / 1024, 256>>>(sentences, snth);
    cvt_f16_kernel<<<((size_t)NHEADS * DMODEL * DHEAD) / 1024, 256>>>(w_s, wsh);

    // 1) S projection (fp16 mma)
    {
        dim3 grid(1, NSENT / 128, NHEADS);
        proj_f16_kernel<<<grid, 256, KPSMEM>>>(snth, wsh, b_s, Sh, DMODEL, NSENT);
    }
    // 2) K projection (fp16 mma)
    {
        dim3 grid(1, NKNOW / 128, NHEADS);
        proj_f16_kernel<<<grid, 256, KPSMEM>>>(Bh, wkh, b_k, Kh, KFDIM, NKNOW);
    }
    // 3) scores + exp -> fp16 e + colsum
    {
        dim3 grid(NKNOW / 128, NSENT / 128, NHEADS);
        scores_f16_kernel<<<grid, 256, SC_SMEM>>>(0.08838834764831845f);
    }
    // 4) fork: attn fp32 write (normalize_b) runs on s2, parallel with
    //    normalize_a + fused on the main stream.
    cudaEventRecord(evFork, 0);
    cudaStreamWaitEvent(s2, evFork, 0);
    {
        dim3 grid(NKNOW / 512, NSENT / 64, NHEADS);
        normalize_b_kernel<<<grid, 256, 0, s2>>>(attn);
    }
    cudaEventRecord(evJoin, s2);

    // 4b) normalize_a (normalized fp16 for the GEMM) on main stream
    {
        dim3 grid(NKNOW / 512, NSENT / 64, NHEADS);
        normalize_a_kernel<<<grid, 256>>>();
    }
    // 5) fused GEMM (R9 config)
    {
        dim3 grid(KFDIM / FBN, NSENT / FBM, NHEADS);
        fused_mma_f16<<<grid, 512, FSMEM>>>(fused);
    }
    // join
    cudaStreamWaitEvent((cudaStream_t)0, evJoin, 0);
}

// round 14
// speedup vs baseline: 1.3212x; 1.0068x over previous
#include <cuda_runtime.h>
#include <cuda_fp16.h>
#include <math.h>
#include <stdint.h>

#define NHEADS 8
#define DMODEL 1024
#define DHEAD  128
#define KFDIM  3072
#define NSENT  2048
#define NKNOW  8192

// Scratch (no cudaMalloc allowed).
__device__ __half g_snth[NSENT * DMODEL];               // 4 MB  sentences fp16
__device__ __half g_wsh[NHEADS * DMODEL * DHEAD];       // 2 MB  w_s fp16
__device__ __half g_Sh[NHEADS * NSENT * DHEAD];         // 4 MB  S fp16
__device__ __half g_Kh[NHEADS * NKNOW * DHEAD];         // 16 MB K fp16
__device__ __half g_wkh[NHEADS * KFDIM * DHEAD];        // 6 MB  w_k fp16
__device__ float  g_colsum[NHEADS * NKNOW];             // 256 KB
__device__ __half g_Ah[(size_t)NHEADS * NSENT * NKNOW]; // 268 MB e fp16
__device__ __half g_An[(size_t)NHEADS * NSENT * NKNOW]; // 268 MB normalized fp16
__device__ __half g_Bh[(size_t)NKNOW * KFDIM];          // 50 MB knowledge fp16

// ===========================================================================
// helpers
// ===========================================================================
__device__ __forceinline__ void mma_f16(float* d, const uint32_t* a, const uint32_t* b) {
    asm volatile(
        "mma.sync.aligned.m16n8k16.row.col.f32.f16.f16.f32 "
        "{%0,%1,%2,%3}, {%4,%5,%6,%7}, {%8,%9}, {%0,%1,%2,%3};"
        : "+f"(d[0]), "+f"(d[1]), "+f"(d[2]), "+f"(d[3])
        : "r"(a[0]), "r"(a[1]), "r"(a[2]), "r"(a[3]), "r"(b[0]), "r"(b[1]));
}
__device__ __forceinline__ void cp_async16(uint32_t dst, const void* src) {
    asm volatile("cp.async.cg.shared.global [%0], [%1], 16;" :: "r"(dst), "l"(src));
}
__device__ __forceinline__ void ldsm_x4(uint32_t* r, uint32_t addr) {
    asm volatile("ldmatrix.sync.aligned.m8n8.x4.shared.b16 {%0,%1,%2,%3}, [%4];"
                 : "=r"(r[0]), "=r"(r[1]), "=r"(r[2]), "=r"(r[3]) : "r"(addr));
}
__device__ __forceinline__ void ldsm_x4_t(uint32_t* r, uint32_t addr) {
    asm volatile("ldmatrix.sync.aligned.m8n8.x4.trans.shared.b16 {%0,%1,%2,%3}, [%4];"
                 : "=r"(r[0]), "=r"(r[1]), "=r"(r[2]), "=r"(r[3]) : "r"(addr));
}

// fp32 -> fp16 (rn)
__global__ __launch_bounds__(256)
void cvt_f16_kernel(const float* __restrict__ in, __half* __restrict__ out)
{
    size_t i = ((size_t)blockIdx.x * 256 + threadIdx.x) * 4;
    float4 v = *(const float4*)(in + i);
    *(__half2*)(out + i)     = __floats2half2_rn(v.x, v.y);
    *(__half2*)(out + i + 2) = __floats2half2_rn(v.z, v.w);
}

// ===========================================================================
// Generic per-head projection on fp16 tensor cores:
//   out[z][m][n] = f16( A[m,:] @ W[z][:,n] + bias[z][n] ),  n < 128
// ===========================================================================
#define KP_STG 4
#define KPA_STR 40
#define KPB_STR 136
#define KPA_H (128 * KPA_STR)
#define KPB_H (32 * KPB_STR)
#define KPSMEM (KP_STG * (KPA_H + KPB_H) * 2)   // 75776 B

__global__ void __launch_bounds__(256, 2)
proj_f16_kernel(const __half* __restrict__ A, const __half* __restrict__ W,
                const float* __restrict__ bias, __half* __restrict__ out,
                int Kdim, int Mtot)
{
    extern __shared__ __half kps[];
    const uint32_t sA = (uint32_t)__cvta_generic_to_shared(kps);
    const uint32_t sB = sA + KP_STG * KPA_H * 2;

    const int tid  = threadIdx.x;
    const int lane = tid & 31;
    const int wid  = tid >> 5;
    const int wm   = wid >> 2;
    const int wn   = wid & 3;
    const int z    = blockIdx.z;
    const int m0   = blockIdx.y * 128;

    const __half* Ap = A + (size_t)m0 * Kdim;
    const __half* Bp = W + (size_t)z * Kdim * DHEAD;

    const int a_r = tid >> 1;
    const int a_c = (tid & 1) << 4;
    const int b_r = tid >> 3;
    const int b_c = (tid & 7) << 4;

    float acc[4][4][4];
#pragma unroll
    for (int mt = 0; mt < 4; mt++)
#pragma unroll
        for (int nt = 0; nt < 4; nt++)
#pragma unroll
            for (int r = 0; r < 4; r++) acc[mt][nt][r] = 0.f;

    const int NT = Kdim / 32;

    auto issue = [&](int kt, int s) {
#pragma unroll
        for (int i = 0; i < 2; i++)
            cp_async16(sA + (uint32_t)(s * KPA_H + a_r * KPA_STR + a_c + 8 * i) * 2,
                       Ap + (size_t)a_r * Kdim + kt * 32 + a_c + 8 * i);
#pragma unroll
        for (int i = 0; i < 2; i++)
            cp_async16(sB + (uint32_t)(s * KPB_H + b_r * KPB_STR + b_c + 8 * i) * 2,
                       Bp + (size_t)(kt * 32 + b_r) * DHEAD + b_c + 8 * i);
        asm volatile("cp.async.commit_group;" ::: "memory");
    };

    issue(0, 0); issue(1, 1); issue(2, 2);

    int scur = 0;
    for (int kt = 0; kt < NT; kt++) {
        if (kt < NT - 2)       asm volatile("cp.async.wait_group 2;" ::: "memory");
        else if (kt == NT - 2) asm volatile("cp.async.wait_group 1;" ::: "memory");
        else                   asm volatile("cp.async.wait_group 0;" ::: "memory");
        __syncthreads();

        if (kt + 3 < NT) {
            int snx = scur + 3; if (snx >= KP_STG) snx -= KP_STG;
            issue(kt + 3, snx);
        }

        const uint32_t aB = sA + (uint32_t)(scur * KPA_H) * 2;
        const uint32_t bB = sB + (uint32_t)(scur * KPB_H) * 2;

#pragma unroll
        for (int ks = 0; ks < 2; ks++) {
            uint32_t bf[4][2];
#pragma unroll
            for (int ntp = 0; ntp < 2; ntp++) {
                uint32_t r[4];
                uint32_t addr = bB + (uint32_t)(((ks * 16 + (lane & 15)) * KPB_STR
                               + wn * 32 + ntp * 16 + ((lane >> 4) << 3)) * 2);
                ldsm_x4_t(r, addr);
                bf[2 * ntp][0]     = r[0];
                bf[2 * ntp][1]     = r[1];
                bf[2 * ntp + 1][0] = r[2];
                bf[2 * ntp + 1][1] = r[3];
            }
#pragma unroll
            for (int mt = 0; mt < 4; mt++) {
                uint32_t af[4];
                uint32_t addr = aB + (uint32_t)(((wm * 64 + mt * 16 + (lane & 15)) * KPA_STR
                               + ks * 16 + ((lane >> 4) << 3)) * 2);
                ldsm_x4(af, addr);
#pragma unroll
                for (int nt = 0; nt < 4; nt++)
                    mma_f16(acc[mt][nt], af, bf[nt]);
            }
        }
        scur++; if (scur >= KP_STG) scur -= KP_STG;
        __syncthreads();
    }

    __half* Op = out + (size_t)z * Mtot * DHEAD;
#pragma unroll
    for (int mt = 0; mt < 4; mt++) {
        const int r = m0 + wm * 64 + mt * 16 + (lane >> 2);
#pragma unroll
        for (int nt = 0; nt < 4; nt++) {
            const int c = wn * 32 + nt * 8 + ((lane & 3) << 1);
            float b0 = bias[z * DHEAD + c], b1 = bias[z * DHEAD + c + 1];
            *(__half2*)(Op + (size_t)r * DHEAD + c) =
                __floats2half2_rn(acc[mt][nt][0] + b0, acc[mt][nt][1] + b1);
            *(__half2*)(Op + (size_t)(r + 8) * DHEAD + c) =
                __floats2half2_rn(acc[mt][nt][2] + b0, acc[mt][nt][3] + b1);
        }
    }
}

// ===========================================================================
// Scores on fp16 tensor cores (NT), CTA tile 128m x 256n, 512 threads
// (16 warps 4x4, warp tile 32x64). fp32 exp; writes fp16 e + colsum.
// ===========================================================================
#define SC_STR 136
#define SC_SMEM ((128 + 256) * SC_STR * 2)   // 104448 B dynamic

__global__ void __launch_bounds__(512, 1)
scores_f16_kernel(float scale)
{
    extern __shared__ __half scs[];
    const uint32_t sA = (uint32_t)__cvta_generic_to_shared(scs);
    const uint32_t sB = sA + 128 * SC_STR * 2;
    __shared__ float red[32][256];

    const int tid  = threadIdx.x;
    const int lane = tid & 31;
    const int wid  = tid >> 5;
    const int wm   = wid >> 2;      // 0..3 (32 rows each)
    const int wn   = wid & 3;       // 0..3 (64 cols each)
    const int z    = blockIdx.z;
    const int m0   = blockIdx.y * 128;
    const int n0   = blockIdx.x * 256;

    const __half* Ap = g_Sh + (size_t)z * NSENT * DHEAD + (size_t)m0 * DHEAD;
    const __half* Bp = g_Kh + (size_t)z * NKNOW * DHEAD + (size_t)n0 * DHEAD;

    // one-shot K=128 load
    {
        const int ra  = tid >> 2;                 // 0..127
        const int ca  = (tid & 3) << 5;           // 0,32,64,96 halves
#pragma unroll
        for (int i = 0; i < 4; i++)
            cp_async16(sA + (uint32_t)(ra * SC_STR + ca + 8 * i) * 2,
                       Ap + (size_t)ra * DHEAD + ca + 8 * i);
        const int rb  = tid >> 1;                 // 0..255
        const int cb  = (tid & 1) << 6;           // 0 or 64 halves
#pragma unroll
        for (int i = 0; i < 8; i++)
            cp_async16(sB + (uint32_t)(rb * SC_STR + cb + 8 * i) * 2,
                       Bp + (size_t)rb * DHEAD + cb + 8 * i);
        asm volatile("cp.async.commit_group;" ::: "memory");
        asm volatile("cp.async.wait_group 0;" ::: "memory");
        __syncthreads();
    }

    float acc[2][8][4];
#pragma unroll
    for (int mt = 0; mt < 2; mt++)
#pragma unroll
        for (int nt = 0; nt < 8; nt++)
#pragma unroll
            for (int r = 0; r < 4; r++) acc[mt][nt][r] = 0.f;

#pragma unroll
    for (int ks = 0; ks < 8; ks++) {
        uint32_t bf[8][2];
#pragma unroll
        for (int ntp = 0; ntp < 4; ntp++) {
            uint32_t r[4];
            uint32_t addr = sB + (uint32_t)(((wn * 64 + ntp * 16 + (lane & 15)) * SC_STR
                           + ks * 16 + ((lane >> 4) << 3)) * 2);
            ldsm_x4(r, addr);                  // rows = n, cols = k (NT)
            bf[2 * ntp][0]     = r[0];
            bf[2 * ntp][1]     = r[2];
            bf[2 * ntp + 1][0] = r[1];
            bf[2 * ntp + 1][1] = r[3];
        }
#pragma unroll
        for (int mt = 0; mt < 2; mt++) {
            uint32_t af[4];
            uint32_t addr = sA + (uint32_t)(((wm * 32 + mt * 16 + (lane & 15)) * SC_STR
                           + ks * 16 + ((lane >> 4) << 3)) * 2);
            ldsm_x4(af, addr);
#pragma unroll
            for (int nt = 0; nt < 8; nt++)
                mma_f16(acc[mt][nt], af, bf[nt]);
        }
    }

    // epilogue: exp (fp32), write fp16 e, column partial sums
    float cp[16];
#pragma unroll
    for (int j = 0; j < 16; j++) cp[j] = 0.f;
    __half* Ep = g_Ah + (size_t)z * NSENT * NKNOW;
#pragma unroll
    for (int mt = 0; mt < 2; mt++) {
        const int r = m0 + wm * 32 + mt * 16 + (lane >> 2);
#pragma unroll
        for (int nt = 0; nt < 8; nt++) {
            const int c = n0 + wn * 64 + nt * 8 + ((lane & 3) << 1);
            float e0 = __expf(acc[mt][nt][0] * scale);
            float e1 = __expf(acc[mt][nt][1] * scale);
            float e2 = __expf(acc[mt][nt][2] * scale);
            float e3 = __expf(acc[mt][nt][3] * scale);
            *(__half2*)(Ep + (size_t)r * NKNOW + c)       = __floats2half2_rn(e0, e1);
            *(__half2*)(Ep + (size_t)(r + 8) * NKNOW + c) = __floats2half2_rn(e2, e3);
            cp[nt * 2]     += e0 + e2;
            cp[nt * 2 + 1] += e1 + e3;
        }
    }
    const int rr = wm * 8 + (lane >> 2);         // 0..31
#pragma unroll
    for (int nt = 0; nt < 8; nt++) {
        red[rr][wn * 64 + nt * 8 + ((lane & 3) << 1)]     = cp[nt * 2];
        red[rr][wn * 64 + nt * 8 + ((lane & 3) << 1) + 1] = cp[nt * 2 + 1];
    }
    __syncthreads();
    if (tid < 256) {
        float s = 0.f;
#pragma unroll
        for (int r = 0; r < 32; r++) s += red[r][tid];
        atomicAdd(&g_colsum[(size_t)z * NKNOW + n0 + tid], s);
    }
}

// ===========================================================================
// normalize_a: g_An = f16( e * 1/colsum )  — feeds the fused GEMM
// ===========================================================================
__global__ __launch_bounds__(256)
void normalize_a_kernel()
{
    const int h = blockIdx.z;
    const int m = (blockIdx.x * 256 + threadIdx.x) * 2;
    const int n0 = blockIdx.y * 64;
    float2 cs = *(const float2*)&g_colsum[(size_t)h * NKNOW + m];
    const float iv0 = 1.f / cs.x, iv1 = 1.f / cs.y;
    const size_t base = (size_t)h * NSENT * NKNOW + (size_t)n0 * NKNOW + m;
    const __half* pe = g_Ah + base;
    __half*       pn = g_An + base;
#pragma unroll 4
    for (int nn = 0; nn < 64; nn++) {
        size_t idx = (size_t)nn * NKNOW;
        __half2 e = *(const __half2*)(pe + idx);
        *(__half2*)(pn + idx) = __floats2half2_rn(__half2float(__low2half(e))  * iv0,
                                                  __half2float(__high2half(e)) * iv1);
    }
}

// ===========================================================================
// normalize_b: attn fp32 = e * 1/colsum  — parallel with fused on stream 2
// ===========================================================================
__global__ __launch_bounds__(256)
void normalize_b_kernel(float* __restrict__ attn)
{
    const int h = blockIdx.z;
    const int m = (blockIdx.x * 256 + threadIdx.x) * 2;
    const int n0 = blockIdx.y * 64;
    float2 cs = *(const float2*)&g_colsum[(size_t)h * NKNOW + m];
    const float iv0 = 1.f / cs.x, iv1 = 1.f / cs.y;
    const size_t base = (size_t)h * NSENT * NKNOW + (size_t)n0 * NKNOW + m;
    const __half* pe = g_Ah + base;
    float*        p  = attn + base;
#pragma unroll 4
    for (int nn = 0; nn < 64; nn++) {
        size_t idx = (size_t)nn * NKNOW;
        __half2 e = *(const __half2*)(pe + idx);
        *(float2*)(p + idx) = make_float2(__half2float(__low2half(e))  * iv0,
                                          __half2float(__high2half(e)) * iv1);
    }
}

// ===========================================================================
// fused = attn_norm_h16 @ knowledge_h16 (fp16 mma, fp32 accum) — R9 config
//   CTA 128x256xK64, 512 thr (16 warps 4x4, warp 32x64), 3-stage cp.async
// ===========================================================================
#define FBM 128
#define FBN 256
#define FBK 64
#define FSTG 3
#define SA_STR 72
#define SB_STR 264
#define SA_H (FBM * SA_STR)
#define SB_H (FBK * SB_STR)
#define FSMEM (FSTG * (SA_H + SB_H) * 2)    // 156672 B

__global__ void __launch_bounds__(512, 1)
fused_mma_f16(float* __restrict__ C)
{
    extern __shared__ __half smh[];
    const uint32_t sA_u32 = (uint32_t)__cvta_generic_to_shared(smh);
    const uint32_t sB_u32 = sA_u32 + FSTG * SA_H * 2;

    const int tid  = threadIdx.x;
    const int lane = tid & 31;
    const int wid  = tid >> 5;
    const int wm   = wid & 3;
    const int wn   = wid >> 2;
    const int z    = blockIdx.z;
    const int m0   = blockIdx.y * FBM;
    const int n0   = blockIdx.x * FBN;

    const __half* Ap = g_An + (size_t)z * NSENT * NKNOW + (size_t)m0 * NKNOW;
    const __half* Bp = g_Bh + n0;

    const int a_row  = tid >> 2;
    const int a_ch   = (tid & 3) << 3;
    const int b_row0 = tid >> 5;
    const int b_ch0  = (tid & 31) << 3;

    float acc[2][8][4];
#pragma unroll
    for (int mt = 0; mt < 2; mt++)
#pragma unroll
        for (int nt = 0; nt < 8; nt++)
#pragma unroll
            for (int r = 0; r < 4; r++) acc[mt][nt][r] = 0.f;

    const int NT = NKNOW / FBK;             // 128

    auto issue = [&](int kt, int s) {
        const __half* abase = Ap + (size_t)kt * FBK;
#pragma unroll
        for (int i = 0; i < 2; i++)
            cp_async16(sA_u32 + (uint32_t)(s * SA_H + a_row * SA_STR + a_ch + 32 * i) * 2,
                       abase + (size_t)a_row * NKNOW + a_ch + 32 * i);
        const __half* bbase = Bp + (size_t)(kt * FBK) * KFDIM;
#pragma unroll
        for (int p = 0; p < 4; p++) {
            int row = b_row0 + p * 16;
            cp_async16(sB_u32 + (uint32_t)(s * SB_H + row * SB_STR + b_ch0) * 2,
                       bbase + (size_t)row * KFDIM + b_ch0);
        }
        asm volatile("cp.async.commit_group;" ::: "memory");
    };

    issue(0, 0); issue(1, 1);

    int scur = 0;
    for (int kt = 0; kt < NT; kt++) {
        if (kt + 1 < NT) asm volatile("cp.async.wait_group 1;" ::: "memory");
        else             asm volatile("cp.async.wait_group 0;" ::: "memory");
        __syncthreads();

        if (kt + 2 < NT) {
            int snx = scur + 2; if (snx >= FSTG) snx -= FSTG;
            issue(kt + 2, snx);
        }

        const uint32_t aBase = sA_u32 + (uint32_t)(scur * SA_H) * 2;
        const uint32_t bBase = sB_u32 + (uint32_t)(scur * SB_H) * 2;

#pragma unroll
        for (int ks = 0; ks < 4; ks++) {
            uint32_t bf[8][2];
#pragma unroll
            for (int ntp = 0; ntp < 4; ntp++) {
                uint32_t r[4];
                uint32_t addr = bBase + (uint32_t)(((ks * 16 + (lane & 15)) * SB_STR
                               + wn * 64 + ntp * 16 + ((lane >> 4) << 3)) * 2);
                ldsm_x4_t(r, addr);
                bf[2 * ntp][0]     = r[0];
                bf[2 * ntp][1]     = r[1];
                bf[2 * ntp + 1][0] = r[2];
                bf[2 * ntp + 1][1] = r[3];
            }
#pragma unroll
            for (int mt = 0; mt < 2; mt++) {
                uint32_t af[4];
                uint32_t addr = aBase + (uint32_t)(((wm * 32 + mt * 16 + (lane & 15)) * SA_STR
                               + ks * 16 + ((lane >> 4) << 3)) * 2);
                ldsm_x4(af, addr);
#pragma unroll
                for (int nt = 0; nt < 8; nt++)
                    mma_f16(acc[mt][nt], af, bf[nt]);
            }
        }
        scur++; if (scur >= FSTG) scur -= FSTG;
    }

    const int ldc = NHEADS * KFDIM;
#pragma unroll
    for (int mt = 0; mt < 2; mt++) {
        const int r = m0 + wm * 32 + mt * 16 + (lane >> 2);
#pragma unroll
        for (int nt = 0; nt < 8; nt++) {
            const int c = z * KFDIM + n0 + wn * 64 + nt * 8 + ((lane & 3) << 1);
            *(float2*)(C + (size_t)r * ldc + c)       = make_float2(acc[mt][nt][0], acc[mt][nt][1]);
            *(float2*)(C + (size_t)(r + 8) * ldc + c) = make_float2(acc[mt][nt][2], acc[mt][nt][3]);
        }
    }
}

// ===========================================================================
// Host side
// ===========================================================================
extern "C" void kernel_launch(void* const* d_in, const int* in_sizes, int n_in,
                              void* d_out, int out_size)
{
    const float* sentences = (const float*)d_in[0];
    const float* knowledge = (const float*)d_in[1];
    const float* w_s       = (const float*)d_in[2];
    const float* b_s       = (const float*)d_in[3];
    const float* w_k       = (const float*)d_in[4];
    const float* b_k       = (const float*)d_in[5];

    float* attn  = (float*)d_out;
    float* fused = (float*)d_out + (size_t)NHEADS * NSENT * NKNOW;

    float* csum = nullptr;
    __half *snth = nullptr, *wsh = nullptr, *Sh = nullptr, *Kh = nullptr,
           *wkh = nullptr, *Bh = nullptr;
    cudaGetSymbolAddress((void**)&csum, g_colsum);
    cudaGetSymbolAddress((void**)&snth, g_snth);
    cudaGetSymbolAddress((void**)&wsh,  g_wsh);
    cudaGetSymbolAddress((void**)&Sh,   g_Sh);
    cudaGetSymbolAddress((void**)&Kh,   g_Kh);
    cudaGetSymbolAddress((void**)&wkh,  g_wkh);
    cudaGetSymbolAddress((void**)&Bh,   g_Bh);

    static cudaStream_t s2;
    static cudaEvent_t evF0, evS, evFork, evJoin;
    static bool init_done = false;
    if (!init_done) {
        cudaFuncSetAttribute(proj_f16_kernel,
                             cudaFuncAttributeMaxDynamicSharedMemorySize, KPSMEM);
        cudaFuncSetAttribute(scores_f16_kernel,
                             cudaFuncAttributeMaxDynamicSharedMemorySize, SC_SMEM);
        cudaFuncSetAttribute(fused_mma_f16,
                             cudaFuncAttributeMaxDynamicSharedMemorySize, FSMEM);
        cudaStreamCreateWithFlags(&s2, cudaStreamNonBlocking);
        cudaEventCreateWithFlags(&evF0,   cudaEventDisableTiming);
        cudaEventCreateWithFlags(&evS,    cudaEventDisableTiming);
        cudaEventCreateWithFlags(&evFork, cudaEventDisableTiming);
        cudaEventCreateWithFlags(&evJoin, cudaEventDisableTiming);
        init_done = true;
    }

    // 0) zero colsums; fork front-end
    cudaMemsetAsync(csum, 0, (size_t)NHEADS * NKNOW * sizeof(float));
    cudaEventRecord(evF0, 0);
    cudaStreamWaitEvent(s2, evF0, 0);

    // s2 branch: sentences chain (cvt -> cvt -> sproj)
    cvt_f16_kernel<<<((size_t)NSENT * DMODEL) / 1024, 256, 0, s2>>>(sentences, snth);
    cvt_f16_kernel<<<((size_t)NHEADS * DMODEL * DHEAD) / 1024, 256, 0, s2>>>(w_s, wsh);
    {
        dim3 grid(1, NSENT / 128, NHEADS);
        proj_f16_kernel<<<grid, 256, KPSMEM, s2>>>(snth, wsh, b_s, Sh, DMODEL, NSENT);
    }
    cudaEventRecord(evS, s2);

    // main branch: knowledge chain (cvt -> cvt -> kproj)
    cvt_f16_kernel<<<((size_t)NKNOW * KFDIM) / 1024, 256>>>(knowledge, Bh);
    cvt_f16_kernel<<<((size_t)NHEADS * KFDIM * DHEAD) / 1024, 256>>>(w_k, wkh);
    {
        dim3 grid(1, NKNOW / 128, NHEADS);
        proj_f16_kernel<<<grid, 256, KPSMEM>>>(Bh, wkh, b_k, Kh, KFDIM, NKNOW);
    }
    cudaStreamWaitEvent((cudaStream_t)0, evS, 0);   // join: scores needs Sh + Kh

    // 3) scores + exp -> fp16 e + colsum  (128m x 256n tiles)
    {
        dim3 grid(NKNOW / 256, NSENT / 128, NHEADS);
        scores_f16_kernel<<<grid, 512, SC_SMEM>>>(0.08838834764831845f);
    }

    // 4) fork: attn fp32 write on s2, parallel with normalize_a + fused
    cudaEventRecord(evFork, 0);
    cudaStreamWaitEvent(s2, evFork, 0);
    {
        dim3 grid(NKNOW / 512, NSENT / 64, NHEADS);
        normalize_b_kernel<<<grid, 256, 0, s2>>>(attn);
    }
    cudaEventRecord(evJoin, s2);

    // 4b) normalize_a (normalized fp16 for the GEMM) on main stream
    {
        dim3 grid(NKNOW / 512, NSENT / 64, NHEADS);
        normalize_a_kernel<<<grid, 256>>>();
    }
    // 5) fused GEMM (R9 config)
    {
        dim3 grid(KFDIM / FBN, NSENT / FBM, NHEADS);
        fused_mma_f16<<<grid, 512, FSMEM>>>(fused);
    }
    // join
    cudaStreamWaitEvent((cudaStream_t)0, evJoin, 0);
}